// round 14
// baseline (speedup 1.0000x reference)
#include <cuda_runtime.h>
#include <cuda_fp16.h>
#include <math.h>

#define BB 8
#define TT 2048
#define DUx 512
#define DMx 512
#define DAx 256
#define DFx 12
#define NSTAGE 4
#define EPSV 1e-6f
#define INV_SCALE (1.0f/16.0f)

// ---------------- scratch (device globals; no allocation) ----------------
__device__ float g_usq[BB*TT];
__device__ float g_sbias[BB*TT];
__device__ float g_base[BB*TT];
__device__ float g_y[BB*TT];
__device__ float g_overlap[BB*TT];
__device__ float g_sp[BB*TT];
__device__ float g_yu[BB*DUx];
__device__ float g_memA[BB*DMx];
__device__ float g_memB[BB*DMx];
__device__ float g_qk[BB*DUx];
__device__ float g_stat[BB*8];     // [ys, coverage, entropy, wsq, spread, csq]
__device__ float g_M[DUx*DMx];     // Wk^T @ Wq
__device__ float g_Wc[3*DMx*DUx];  // W_ih[:, :512] @ Wv  (1536 x 512)
__device__ float g_gh[BB*3*DMx];   // W_hh @ mem + b_hh
__device__ float g_gi[BB*3*DMx];   // W_comb @ yu + b_ih

__device__ __half g_simh[(size_t)BB*TT*TT];   // 67 MB
__device__ __half g_uh[(size_t)BB*TT*DUx];    // 17 MB

// ---------------- reduction helpers ----------------
__device__ __forceinline__ float warpSum(float v){
    #pragma unroll
    for (int o = 16; o; o >>= 1) v += __shfl_xor_sync(0xffffffffu, v, o);
    return v;
}
__device__ __forceinline__ float warpMax(float v){
    #pragma unroll
    for (int o = 16; o; o >>= 1) v = fmaxf(v, __shfl_xor_sync(0xffffffffu, v, o));
    return v;
}
__device__ __forceinline__ float blockSum(float v, float* sh){
    int lane = threadIdx.x & 31, w = threadIdx.x >> 5;
    int nw = (blockDim.x + 31) >> 5;
    v = warpSum(v);
    if (lane == 0) sh[w] = v;
    __syncthreads();
    if (w == 0){
        float x = (lane < nw) ? sh[lane] : 0.f;
        x = warpSum(x);
        if (lane == 0) sh[0] = x;
    }
    __syncthreads();
    float r = sh[0];
    __syncthreads();
    return r;
}
__device__ __forceinline__ float blockMax(float v, float* sh){
    int lane = threadIdx.x & 31, w = threadIdx.x >> 5;
    int nw = (blockDim.x + 31) >> 5;
    v = warpMax(v);
    if (lane == 0) sh[w] = v;
    __syncthreads();
    if (w == 0){
        float x = (lane < nw) ? sh[lane] : -INFINITY;
        x = warpMax(x);
        if (lane == 0) sh[0] = x;
    }
    __syncthreads();
    float r = sh[0];
    __syncthreads();
    return r;
}
__device__ __forceinline__ void clusterSync(){
    asm volatile("barrier.cluster.arrive.aligned;" ::: "memory");
    asm volatile("barrier.cluster.wait.aligned;" ::: "memory");
}

// ---------------- sim fp32 -> fp16 (s2, overlapped with prologue) ----------------
__global__ void k_conv(const float* __restrict__ sim){
    size_t i = ((size_t)blockIdx.x * blockDim.x + threadIdx.x) * 2;
    const float4* in = (const float4*)sim;
    int4* outp = (int4*)g_simh;
    #pragma unroll
    for (int k = 0; k < 2; k++){
        size_t ii = i + k;
        float4 f0 = in[2*ii], f1 = in[2*ii+1];
        __half2 h0 = __floats2half2_rn(f0.x, f0.y);
        __half2 h1 = __floats2half2_rn(f0.z, f0.w);
        __half2 h2 = __floats2half2_rn(f1.x, f1.y);
        __half2 h3 = __floats2half2_rn(f1.z, f1.w);
        int4 o;
        o.x = *(int*)&h0; o.y = *(int*)&h1; o.z = *(int*)&h2; o.w = *(int*)&h3;
        outp[ii] = o;
    }
}

// ---------------- init ----------------
__global__ void k_init(const float* __restrict__ mem0){
    int i = blockIdx.x * blockDim.x + threadIdx.x;
    if (i < BB*TT) g_sp[i] = 0.f;
    if (i < BB*DMx) g_memA[i] = mem0[i];
}

// ---------------- M = Wk^T @ Wq ----------------
__global__ void k_Mpre(const float* __restrict__ Wk, const float* __restrict__ Wq){
    int bm = blockIdx.x & 15, bd = blockIdx.x >> 4;
    int d0 = bd*32, m0 = bm*32;
    __shared__ float sA[32*32];
    __shared__ float sB[32*32];
    float acc[4] = {0.f, 0.f, 0.f, 0.f};
    int tx = threadIdx.x & 31, ty = threadIdx.x >> 5;
    for (int a0 = 0; a0 < DAx; a0 += 32){
        __syncthreads();
        for (int i = threadIdx.x; i < 1024; i += 256){
            int ar = i >> 5, col = i & 31;
            sA[i] = Wk[(size_t)(a0+ar)*DUx + d0 + col];
            sB[i] = Wq[(size_t)(a0+ar)*DMx + m0 + col];
        }
        __syncthreads();
        #pragma unroll
        for (int aa = 0; aa < 32; aa++){
            float bv = sB[aa*32 + tx];
            #pragma unroll
            for (int r = 0; r < 4; r++)
                acc[r] += sA[aa*32 + ty + r*8] * bv;
        }
    }
    #pragma unroll
    for (int r = 0; r < 4; r++)
        g_M[(size_t)(d0 + ty + r*8)*DMx + m0 + tx] = acc[r];
}

// ---------------- W_comb = W_ih[:, :512] @ Wv ----------------
__global__ void k_Wcomb(const float* __restrict__ Wih, const float* __restrict__ Wv){
    int bc = blockIdx.x & 15, br = blockIdx.x >> 4;
    int r0 = br*32, c0 = bc*32;
    __shared__ float sA[32*32];
    __shared__ float sB[32*32];
    float acc[4] = {0.f, 0.f, 0.f, 0.f};
    int tx = threadIdx.x & 31, ty = threadIdx.x >> 5;
    for (int k0 = 0; k0 < DUx; k0 += 32){
        __syncthreads();
        for (int i = threadIdx.x; i < 1024; i += 256){
            int ar = i >> 5, col = i & 31;
            sA[i] = Wih[(size_t)(r0+ar)*516 + k0 + col];
            sB[i] = Wv[(size_t)(k0+ar)*DUx + c0 + col];
        }
        __syncthreads();
        #pragma unroll
        for (int kk = 0; kk < 32; kk++){
            float bv = sB[kk*32 + tx];
            #pragma unroll
            for (int r = 0; r < 4; r++)
                acc[r] += sA[(ty + r*8)*32 + kk] * bv;
        }
    }
    #pragma unroll
    for (int r = 0; r < 4; r++)
        g_Wc[(size_t)(r0 + ty + r*8)*DUx + c0 + tx] = acc[r];
}

// ---------------- precompute: usq, sbias, u->fp16; 2 rows/warp ----------------
__global__ void k_pre(const float* __restrict__ u, const float* __restrict__ sf,
                      const float* __restrict__ w1, const float* __restrict__ b1,
                      const float* __restrict__ w2, const float* __restrict__ b2){
    int b  = blockIdx.x >> 7;
    int t0 = (blockIdx.x & 127) * 16;
    int w = threadIdx.x >> 5, lane = threadIdx.x & 31;
    int tA = t0 + w, tB = t0 + w + 8;
    int btA = b*TT + tA, btB = b*TT + tB;
    const float4* upA = (const float4*)(u + (size_t)btA * DUx);
    const float4* upB = (const float4*)(u + (size_t)btB * DUx);
    int4* uoA = (int4*)(g_uh + (size_t)btA * DUx);
    int4* uoB = (int4*)(g_uh + (size_t)btB * DUx);
    float accA = 0.f, accB = 0.f;
    #pragma unroll
    for (int c = 0; c < 2; c++){
        int idx = c*32 + lane;
        float4 a0 = upA[2*idx], a1 = upA[2*idx+1];
        float4 b0 = upB[2*idx], b1v = upB[2*idx+1];
        accA += a0.x*a0.x + a0.y*a0.y + a0.z*a0.z + a0.w*a0.w
              + a1.x*a1.x + a1.y*a1.y + a1.z*a1.z + a1.w*a1.w;
        accB += b0.x*b0.x + b0.y*b0.y + b0.z*b0.z + b0.w*b0.w
              + b1v.x*b1v.x + b1v.y*b1v.y + b1v.z*b1v.z + b1v.w*b1v.w;
        __half2 hA0 = __floats2half2_rn(a0.x, a0.y), hA1 = __floats2half2_rn(a0.z, a0.w);
        __half2 hA2 = __floats2half2_rn(a1.x, a1.y), hA3 = __floats2half2_rn(a1.z, a1.w);
        __half2 hB0 = __floats2half2_rn(b0.x, b0.y), hB1 = __floats2half2_rn(b0.z, b0.w);
        __half2 hB2 = __floats2half2_rn(b1v.x, b1v.y), hB3 = __floats2half2_rn(b1v.z, b1v.w);
        int4 oA, oB;
        oA.x = *(int*)&hA0; oA.y = *(int*)&hA1; oA.z = *(int*)&hA2; oA.w = *(int*)&hA3;
        oB.x = *(int*)&hB0; oB.y = *(int*)&hB1; oB.z = *(int*)&hB2; oB.w = *(int*)&hB3;
        uoA[idx] = oA; uoB[idx] = oB;
    }
    accA = warpSum(accA); accB = warpSum(accB);
    float dA0 = sf[btA*DFx + 8], dA1 = sf[btA*DFx + 9], dA2 = sf[btA*DFx + 10];
    float dB0 = sf[btB*DFx + 8], dB1 = sf[btB*DFx + 9], dB2 = sf[btB*DFx + 10];
    float sbA = 0.f, sbB = 0.f;
    #pragma unroll
    for (int k = 0; k < 8; k++){
        int a = lane + k*32;
        float w1a = w1[a*3+0], w1b = w1[a*3+1], w1c = w1[a*3+2], bb = b1[a], w2a = w2[a];
        float hA = w1a*dA0 + w1b*dA1 + w1c*dA2 + bb;
        float hB = w1a*dB0 + w1b*dB1 + w1c*dB2 + bb;
        hA = 0.5f * hA * (1.f + erff(hA * 0.70710678118654752f));
        hB = 0.5f * hB * (1.f + erff(hB * 0.70710678118654752f));
        sbA += hA * w2a; sbB += hB * w2a;
    }
    sbA = warpSum(sbA); sbB = warpSum(sbB);
    if (lane == 0){
        g_usq[btA] = accA; g_sbias[btA] = sbA + b2[0];
        g_usq[btB] = accB; g_sbias[btB] = sbB + b2[0];
    }
}

// ---------------- qk (prologue only) ----------------
__global__ void k_qk(int inB){
    const float* mem_in = inB ? g_memB : g_memA;
    int b = blockIdx.x >> 4;
    int c = blockIdx.x & 15;
    __shared__ float4 s_m4[DMx/4];
    for (int i = threadIdx.x; i < DMx/4; i += 256)
        s_m4[i] = ((const float4*)(mem_in + b*DMx))[i];
    __syncthreads();
    int w = threadIdx.x >> 5, lane = threadIdx.x & 31;
    #pragma unroll
    for (int j = 0; j < 4; j++){
        int d = c*32 + w*4 + j;
        const float4* row = (const float4*)(g_M + (size_t)d * DMx);
        float acc = 0.f;
        #pragma unroll
        for (int cc = 0; cc < 4; cc++){
            int idx = cc*32 + lane;
            float4 a = row[idx], m4 = s_m4[idx];
            acc += a.x*m4.x + a.y*m4.y + a.z*m4.z + a.w*m4.w;
        }
        acc = warpSum(acc);
        if (lane == 0) g_qk[b*DUx + d] = acc;
    }
}

// ---------------- scores (prologue only) ----------------
__global__ void k_scores(){
    int b  = blockIdx.x >> 7;
    int t0 = (blockIdx.x & 127) * 16;
    __shared__ float2 s_qk2[DUx/2];
    for (int i = threadIdx.x; i < DUx/2; i += blockDim.x)
        s_qk2[i] = ((const float2*)(g_qk + b*DUx))[i];
    __syncthreads();
    int w = threadIdx.x >> 5, lane = threadIdx.x & 31;
    int btA = b*TT + t0 + w, btB = btA + 8;
    const int4* rA = (const int4*)(g_uh + (size_t)btA * DUx);
    const int4* rB = (const int4*)(g_uh + (size_t)btB * DUx);
    int4 hA0 = rA[lane], hA1 = rA[32+lane];
    int4 hB0 = rB[lane], hB1 = rB[32+lane];
    float accA = 0.f, accB = 0.f;
    {
        __half2* pA0 = (__half2*)&hA0; __half2* pA1 = (__half2*)&hA1;
        __half2* pB0 = (__half2*)&hB0; __half2* pB1 = (__half2*)&hB1;
        #pragma unroll
        for (int j = 0; j < 4; j++){
            float2 q0 = s_qk2[lane*4 + j];
            float2 q1 = s_qk2[(32+lane)*4 + j];
            float2 a0 = __half22float2(pA0[j]), a1 = __half22float2(pA1[j]);
            float2 b0 = __half22float2(pB0[j]), b1v = __half22float2(pB1[j]);
            accA += a0.x*q0.x + a0.y*q0.y + a1.x*q1.x + a1.y*q1.y;
            accB += b0.x*q0.x + b0.y*q0.y + b1v.x*q1.x + b1v.y*q1.y;
        }
    }
    accA = warpSum(accA); accB = warpSum(accB);
    if (lane == 0){
        g_base[btA] = accA * INV_SCALE + g_sbias[btA];
        g_base[btB] = accB * INV_SCALE + g_sbias[btB];
    }
}

// ---------------- softmax((base-sp)/temp) + overlap (fp16 sim); 2 rows/warp ----------------
__global__ void k_simmv_ov(const float* __restrict__ lt){
    int b  = blockIdx.x >> 7;
    int t0 = (blockIdx.x & 127) * 16;
    __shared__ float2 s_y2[TT/2];
    __shared__ float sh[32];
    float temp = fminf(fmaxf(expf(lt[0]), 0.1f), 10.f);
    float invT = 1.f / temp;
    float lv[8];
    float mloc = -INFINITY;
    #pragma unroll
    for (int k = 0; k < 8; k++){
        int j = threadIdx.x + k*256;
        lv[k] = (g_base[b*TT+j] - g_sp[b*TT+j]) * invT;
        mloc = fmaxf(mloc, lv[k]);
    }
    float m = blockMax(mloc, sh);
    float se = 0.f;
    #pragma unroll
    for (int k = 0; k < 8; k++){
        int j = threadIdx.x + k*256;
        float e = expf(lv[k] - m);
        ((float*)s_y2)[j] = e;
        se += e;
    }
    float S = blockSum(se, sh);
    float invS = 1.f / S;
    int w = threadIdx.x >> 5, lane = threadIdx.x & 31;
    int btA = b*TT + t0 + w, btB = btA + 8;
    const int4* rowA = (const int4*)(g_simh + (size_t)btA * TT);
    const int4* rowB = (const int4*)(g_simh + (size_t)btB * TT);
    float accA = 0.f, accB = 0.f;
    #pragma unroll
    for (int c = 0; c < 8; c++){
        int idx = c*32 + lane;
        int4 hA = rowA[idx], hB = rowB[idx];
        __half2* pA = (__half2*)&hA; __half2* pB = (__half2*)&hB;
        #pragma unroll
        for (int j = 0; j < 4; j++){
            float2 yv = s_y2[idx*4 + j];
            float2 sa = __half22float2(pA[j]);
            float2 sb = __half22float2(pB[j]);
            accA += sa.x*yv.x + sa.y*yv.y;
            accB += sb.x*yv.x + sb.y*yv.y;
        }
    }
    accA = warpSum(accA); accB = warpSum(accB);
    if (lane == 0){
        g_overlap[btA] = accA * invS;
        g_overlap[btB] = accB * invS;
    }
}

// ---------------- sp += sim @ y_final (side stream); 2 rows/warp ----------------
__global__ void k_simmv_sp(){
    int b  = blockIdx.x >> 7;
    int t0 = (blockIdx.x & 127) * 16;
    __shared__ float2 s_y2[TT/2];
    for (int i = threadIdx.x; i < TT/2; i += blockDim.x)
        s_y2[i] = ((const float2*)(g_y + b*TT))[i];
    __syncthreads();
    int w = threadIdx.x >> 5, lane = threadIdx.x & 31;
    int btA = b*TT + t0 + w, btB = btA + 8;
    const int4* rowA = (const int4*)(g_simh + (size_t)btA * TT);
    const int4* rowB = (const int4*)(g_simh + (size_t)btB * TT);
    float accA = 0.f, accB = 0.f;
    #pragma unroll
    for (int c = 0; c < 8; c++){
        int idx = c*32 + lane;
        int4 hA = rowA[idx], hB = rowB[idx];
        __half2* pA = (__half2*)&hA; __half2* pB = (__half2*)&hB;
        #pragma unroll
        for (int j = 0; j < 4; j++){
            float2 yv = s_y2[idx*4 + j];
            float2 sa = __half22float2(pA[j]);
            float2 sb = __half22float2(pB[j]);
            accA += sa.x*yv.x + sa.y*yv.y;
            accB += sb.x*yv.x + sb.y*yv.y;
        }
    }
    accA = warpSum(accA); accB = warpSum(accB);
    if (lane == 0){
        g_sp[btA] += accA;
        g_sp[btB] += accB;
    }
}

// ---------------- penalty + second softmax + scalar stats ----------------
__global__ void k_penalty(const float* __restrict__ lt){
    int b = blockIdx.x;
    int i0 = b*TT + threadIdx.x, i1 = i0 + 1024;
    __shared__ float sh[32];
    float temp = fminf(fmaxf(expf(lt[0]), 0.1f), 10.f);
    float invT = 1.f / temp;
    float o0 = g_overlap[i0], o1 = g_overlap[i1];
    float mo = blockMax(fmaxf(o0, o1), sh);
    mo = fmaxf(mo, EPSV);
    float invmo = 1.f / mo;
    float l0 = (g_base[i0] - g_sp[i0]) * invT - o0*invmo;
    float l1 = (g_base[i1] - g_sp[i1]) * invT - o1*invmo;
    float m = blockMax(fmaxf(l0, l1), sh);
    float e0 = expf(l0 - m), e1 = expf(l1 - m);
    float S = blockSum(e0 + e1, sh);
    float invS = 1.f / S;
    float y0 = e0*invS, y1 = e1*invS;
    g_y[i0] = y0; g_y[i1] = y1;
    float ysum = blockSum(y0 + y1, sh);
    float ys = fmaxf(ysum, EPSV);
    float invys = 1.f / ys;
    float yn0 = y0*invys, yn1 = y1*invys;
    float ent = blockSum(-yn0*logf(fmaxf(yn0, EPSV)) - yn1*logf(fmaxf(yn1, EPSV)), sh);
    float wsq = blockSum(y0*g_usq[i0] + y1*g_usq[i1], sh);
    if (threadIdx.x == 0){
        g_stat[b*8+0] = ys;
        g_stat[b*8+1] = ysum * (1.f/(float)TT);
        g_stat[b*8+2] = ent;
        g_stat[b*8+3] = wsq;
        g_stat[b*8+4] = 0.f;
    }
    if (threadIdx.x < DUx) g_yu[b*DUx + threadIdx.x] = 0.f;
}

// ---------------- STAGE MEGAKERNEL: cluster of 8 CTAs per batch ----------------
// P0: yu (ranks 0-3) || gh (ranks 4-7)
// P1: dist+csq (ranks 0-3) || gimain + zx (ranks 4-7)
// P2: grufin (rank 0)
// P3: qk   (skip if last)
// P4: scores (skip if last)
__global__ void __cluster_dims__(8,1,1) __launch_bounds__(512)
k_stage(const float* __restrict__ Wih, const float* __restrict__ bih,
        const float* __restrict__ Whh, const float* __restrict__ bhh,
        const float* __restrict__ Wv, float* __restrict__ out,
        int stage, int inB, int last){
    int b    = blockIdx.x >> 3;
    int rank = blockIdx.x & 7;
    int tid  = threadIdx.x;
    int w = tid >> 5, lane = tid & 31;   // 16 warps
    const float* mem_in  = inB ? g_memB : g_memA;
    float*       mem_out = inB ? g_memA : g_memB;
    __shared__ float4 s_buf4[128];
    __shared__ float sh[32];
    float* s_buf = (float*)s_buf4;

    // ================= P0 =================
    if (rank < 4){
        // yu partial over t in [rank*512, +512)
        int tb = rank*512;
        s_buf[tid] = g_y[b*TT + tb + tid];
        __syncthreads();
        int g = tid >> 8, l = tid & 255;
        const __half2* up = (const __half2*)(g_uh + ((size_t)b*TT + tb + g*256) * DUx);
        float ax = 0.f, ay = 0.f;
        #pragma unroll 8
        for (int i = 0; i < 256; i++){
            float yv = s_buf[g*256 + i];
            float2 v = __half22float2(up[(size_t)i*256 + l]);
            ax += yv*v.x; ay += yv*v.y;
        }
        atomicAdd(&g_yu[b*DUx + 2*l],   ax);
        atomicAdd(&g_yu[b*DUx + 2*l+1], ay);
    } else {
        // gh rows [(rank-4)*384, +384): 16 warps x 24 rows
        s_buf[tid] = mem_in[b*DMx + tid];
        __syncthreads();
        int rb = (rank-4)*384 + w*24;
        for (int k = 0; k < 24; k++){
            int r = rb + k;
            const float4* row = (const float4*)(Whh + (size_t)r * DMx);
            float acc = 0.f;
            #pragma unroll
            for (int c = 0; c < 4; c++){
                float4 a = row[c*32+lane];
                float4 m = s_buf4[c*32+lane];
                acc += a.x*m.x + a.y*m.y + a.z*m.z + a.w*m.w;
            }
            acc = warpSum(acc);
            if (lane == 0) g_gh[b*1536 + r] = acc + bhh[r];
        }
    }
    __threadfence();
    clusterSync();

    // ================= P1 =================
    if (rank < 4){
        // dist over t in [rank*512, +512); rank 0 also csq
        float ys = g_stat[b*8+0];
        float invys = 1.f / ys;
        __syncthreads();
        s_buf[tid] = g_yu[b*DUx + tid] * invys;   // cen
        __syncthreads();
        if (rank == 0){
            float yv = g_yu[b*DUx + tid];
            float v = blockSum(yv*yv, sh);
            if (tid == 0) g_stat[b*8+5] = v;      // csq = sum(yu^2)
        }
        float part = 0.f;
        int tb = rank*512 + w*32;
        for (int k = 0; k < 32; k++){
            int bt = b*TT + tb + k;
            const int4* rowh = (const int4*)(g_uh + (size_t)bt * DUx);
            float acc = 0.f;
            #pragma unroll
            for (int c2 = 0; c2 < 2; c2++){
                int idx = c2*32 + lane;
                int4 h = rowh[idx];
                __half2* hp = (__half2*)&h;
                #pragma unroll
                for (int j = 0; j < 4; j++){
                    float2 uv = __half22float2(hp[j]);
                    float2 cn = ((float2*)s_buf)[idx*4 + j];
                    float dx = uv.x - cn.x, dy = uv.y - cn.y;
                    acc += dx*dx + dy*dy;
                }
            }
            acc = warpSum(acc);
            if (lane == 0) part += g_y[bt] * sqrtf(acc);
        }
        float tot = blockSum((lane == 0) ? part : 0.f, sh);
        if (tid == 0) atomicAdd(&g_stat[b*8+4], tot);
    } else {
        // gimain rows (0..1535) + zx rows (1536..2047): 512 rows per CTA
        __syncthreads();
        s_buf[tid] = g_yu[b*DUx + tid];
        __syncthreads();
        int rb = (rank-4)*512 + w*32;
        for (int k = 0; k < 32; k++){
            int r = rb + k;
            const float4* row = (r < 1536) ? (const float4*)(g_Wc + (size_t)r * DUx)
                                           : (const float4*)(Wv + (size_t)(r-1536) * DUx);
            float acc = 0.f;
            #pragma unroll
            for (int c = 0; c < 4; c++){
                float4 a = row[c*32+lane];
                float4 m = s_buf4[c*32+lane];
                acc += a.x*m.x + a.y*m.y + a.z*m.z + a.w*m.w;
            }
            acc = warpSum(acc);
            if (lane == 0){
                if (r < 1536) g_gi[b*1536 + r] = acc + bih[r];
                else          out[((size_t)b*NSTAGE + stage)*DUx + (r-1536)] = acc;
            }
        }
    }
    __threadfence();
    clusterSync();

    // ================= P2: grufin (rank 0) =================
    if (rank == 0){
        __syncthreads();
        if (tid == 0){
            float ys = g_stat[b*8+0];
            s_buf[0] = g_stat[b*8+1];
            s_buf[1] = g_stat[b*8+2];
            s_buf[2] = g_stat[b*8+4] / ys;
            s_buf[3] = 2.f*(ys*g_stat[b*8+3] - g_stat[b*8+5]) / fmaxf(ys*ys, EPSV);
        }
        __syncthreads();
        int j = tid;
        float gi[3], gh[3];
        #pragma unroll
        for (int g = 0; g < 3; g++){
            int r = j + g*DMx;
            const float4 tl = *(const float4*)(Wih + (size_t)r * 516 + 512);
            gi[g] = g_gi[b*1536 + r]
                  + tl.x*s_buf[0] + tl.y*s_buf[1] + tl.z*s_buf[2] + tl.w*s_buf[3];
            gh[g] = g_gh[b*1536 + r];
        }
        float rg = 1.f / (1.f + expf(-(gi[0] + gh[0])));
        float zg = 1.f / (1.f + expf(-(gi[1] + gh[1])));
        float ng = tanhf(gi[2] + rg * gh[2]);
        mem_out[b*DMx + j] = (1.f - zg) * ng + zg * mem_in[b*DMx + j];
    }
    __threadfence();
    clusterSync();

    if (last) return;

    // ================= P3: qk (64 rows/CTA) =================
    __syncthreads();
    s_buf[tid] = mem_out[b*DMx + tid];
    __syncthreads();
    {
        int db = rank*64 + w*4;
        #pragma unroll
        for (int k = 0; k < 4; k++){
            int d = db + k;
            const float4* row = (const float4*)(g_M + (size_t)d * DMx);
            float acc = 0.f;
            #pragma unroll
            for (int c = 0; c < 4; c++){
                float4 a = row[c*32+lane];
                float4 m = s_buf4[c*32+lane];
                acc += a.x*m.x + a.y*m.y + a.z*m.z + a.w*m.w;
            }
            acc = warpSum(acc);
            if (lane == 0) g_qk[b*DUx + d] = acc;
        }
    }
    __threadfence();
    clusterSync();

    // ================= P4: scores (256 t-rows/CTA) =================
    __syncthreads();
    s_buf[tid] = g_qk[b*DUx + tid];
    __syncthreads();
    {
        const float2* s_qk2 = (const float2*)s_buf;
        int tb = rank*256;
        for (int p = 0; p < 8; p++){
            int tA = tb + p*32 + w*2;
            int btA = b*TT + tA, btB = btA + 1;
            const int4* rA = (const int4*)(g_uh + (size_t)btA * DUx);
            const int4* rB = (const int4*)(g_uh + (size_t)btB * DUx);
            int4 hA0 = rA[lane], hA1 = rA[32+lane];
            int4 hB0 = rB[lane], hB1 = rB[32+lane];
            float accA = 0.f, accB = 0.f;
            __half2* pA0 = (__half2*)&hA0; __half2* pA1 = (__half2*)&hA1;
            __half2* pB0 = (__half2*)&hB0; __half2* pB1 = (__half2*)&hB1;
            #pragma unroll
            for (int j = 0; j < 4; j++){
                float2 q0 = s_qk2[lane*4 + j];
                float2 q1 = s_qk2[(32+lane)*4 + j];
                float2 a0 = __half22float2(pA0[j]), a1 = __half22float2(pA1[j]);
                float2 b0 = __half22float2(pB0[j]), b1v = __half22float2(pB1[j]);
                accA += a0.x*q0.x + a0.y*q0.y + a1.x*q1.x + a1.y*q1.y;
                accB += b0.x*q0.x + b0.y*q0.y + b1v.x*q1.x + b1v.y*q1.y;
            }
            accA = warpSum(accA); accB = warpSum(accB);
            if (lane == 0){
                g_base[btA] = accA * INV_SCALE + g_sbias[btA];
                g_base[btB] = accB * INV_SCALE + g_sbias[btB];
            }
        }
    }
}

// ---------------- launch ----------------
extern "C" void kernel_launch(void* const* d_in, const int* in_sizes, int n_in,
                              void* d_out, int out_size){
    const float* u    = (const float*)d_in[0];
    const float* sf   = (const float*)d_in[1];
    const float* sim  = (const float*)d_in[2];
    const float* mem0 = (const float*)d_in[3];
    const float* Wq   = (const float*)d_in[4];
    const float* Wk   = (const float*)d_in[5];
    const float* Wv   = (const float*)d_in[6];
    const float* sbw1 = (const float*)d_in[7];
    const float* sbb1 = (const float*)d_in[8];
    const float* sbw2 = (const float*)d_in[9];
    const float* sbb2 = (const float*)d_in[10];
    const float* lt   = (const float*)d_in[11];
    const float* Wih  = (const float*)d_in[12];
    const float* bih  = (const float*)d_in[13];
    const float* Whh  = (const float*)d_in[14];
    const float* bhh  = (const float*)d_in[15];
    float* out = (float*)d_out;

    static cudaStream_t s2 = nullptr, s3 = nullptr;
    static cudaEvent_t evR, evM, evC, evW, evF[3], evJ[3];
    if (s2 == nullptr){
        cudaStreamCreateWithFlags(&s2, cudaStreamNonBlocking);
        cudaStreamCreateWithFlags(&s3, cudaStreamNonBlocking);
        cudaEventCreateWithFlags(&evR, cudaEventDisableTiming);
        cudaEventCreateWithFlags(&evM, cudaEventDisableTiming);
        cudaEventCreateWithFlags(&evC, cudaEventDisableTiming);
        cudaEventCreateWithFlags(&evW, cudaEventDisableTiming);
        for (int i = 0; i < 3; i++){
            cudaEventCreateWithFlags(&evF[i], cudaEventDisableTiming);
            cudaEventCreateWithFlags(&evJ[i], cudaEventDisableTiming);
        }
    }

    // prologue: s2 = sim conversion; s3 = init+Mpre+Wcomb; main = pre+qk+scores
    cudaEventRecord(evR, 0);
    cudaStreamWaitEvent(s2, evR, 0);
    cudaStreamWaitEvent(s3, evR, 0);
    k_conv<<<8192, 256, 0, s2>>>(sim);
    cudaEventRecord(evC, s2);
    k_init<<<64, 256, 0, s3>>>(mem0);
    k_Mpre<<<256, 256, 0, s3>>>(Wk, Wq);
    cudaEventRecord(evM, s3);                          // M + memA + sp=0 ready
    k_Wcomb<<<768, 256, 0, s3>>>(Wih, Wv);
    cudaEventRecord(evW, s3);
    k_pre<<<BB*TT/16, 256>>>(u, sf, sbw1, sbb1, sbw2, sbb2);
    cudaStreamWaitEvent(0, evM, 0);
    k_qk<<<BB*16, 256>>>(0);
    k_scores<<<BB*TT/16, 256>>>();
    cudaStreamWaitEvent(0, evC, 0);                    // fp16 sim ready

    for (int s = 0; s < NSTAGE; s++){
        if (s > 0) cudaStreamWaitEvent(0, evJ[s-1], 0);   // sp ready
        k_simmv_ov<<<BB*TT/16, 256>>>(lt);                // softmax + fp16 overlap
        k_penalty<<<BB, 1024>>>(lt);                      // y_final + stats (+zero yu/spread)
        if (s < NSTAGE - 1){
            cudaEventRecord(evF[s], 0);
            cudaStreamWaitEvent(s2, evF[s], 0);
            k_simmv_sp<<<BB*TT/16, 256, 0, s2>>>();       // hidden under megakernel
            cudaEventRecord(evJ[s], s2);
        }
        if (s == 0) cudaStreamWaitEvent(0, evW, 0);       // Wc ready
        k_stage<<<64, 512>>>(Wih, bih, Whh, bhh, Wv, out,
                             s, s & 1, (s == NSTAGE-1) ? 1 : 0);
    }
}

// round 15
// speedup vs baseline: 1.2771x; 1.2771x over previous
#include <cuda_runtime.h>
#include <cuda_fp16.h>
#include <math.h>

#define BB 8
#define TT 2048
#define DUx 512
#define DMx 512
#define DAx 256
#define DFx 12
#define NSTAGE 4
#define EPSV 1e-6f
#define INV_SCALE (1.0f/16.0f)

// ---------------- scratch (device globals; no allocation) ----------------
__device__ float g_usq[BB*TT];
__device__ float g_sbias[BB*TT];
__device__ float g_base[BB*TT];
__device__ float g_y[BB*TT];
__device__ float g_overlap[BB*TT];
__device__ float g_sp[BB*TT];
__device__ float g_yu[BB*DUx];
__device__ float g_memA[BB*DMx];
__device__ float g_memB[BB*DMx];
__device__ float g_qk[BB*DUx];
__device__ float g_stat[BB*8];     // [ys, coverage, entropy, wsq, spread, csq]
__device__ float g_M[DUx*DMx];     // Wk^T @ Wq
__device__ float g_Wc[3*DMx*DUx];  // W_ih[:, :512] @ Wv  (1536 x 512)
__device__ float g_gh[BB*3*DMx];   // W_hh @ mem + b_hh
__device__ float g_gi[BB*3*DMx];   // W_comb @ yu + b_ih

__device__ __half g_simh[(size_t)BB*TT*TT];   // 67 MB
__device__ __half g_uh[(size_t)BB*TT*DUx];    // 17 MB

// ---------------- reduction helpers ----------------
__device__ __forceinline__ float warpSum(float v){
    #pragma unroll
    for (int o = 16; o; o >>= 1) v += __shfl_xor_sync(0xffffffffu, v, o);
    return v;
}
__device__ __forceinline__ float warpMax(float v){
    #pragma unroll
    for (int o = 16; o; o >>= 1) v = fmaxf(v, __shfl_xor_sync(0xffffffffu, v, o));
    return v;
}
__device__ __forceinline__ float blockSum(float v, float* sh){
    int lane = threadIdx.x & 31, w = threadIdx.x >> 5;
    int nw = (blockDim.x + 31) >> 5;
    v = warpSum(v);
    if (lane == 0) sh[w] = v;
    __syncthreads();
    if (w == 0){
        float x = (lane < nw) ? sh[lane] : 0.f;
        x = warpSum(x);
        if (lane == 0) sh[0] = x;
    }
    __syncthreads();
    float r = sh[0];
    __syncthreads();
    return r;
}
__device__ __forceinline__ float blockMax(float v, float* sh){
    int lane = threadIdx.x & 31, w = threadIdx.x >> 5;
    int nw = (blockDim.x + 31) >> 5;
    v = warpMax(v);
    if (lane == 0) sh[w] = v;
    __syncthreads();
    if (w == 0){
        float x = (lane < nw) ? sh[lane] : -INFINITY;
        x = warpMax(x);
        if (lane == 0) sh[0] = x;
    }
    __syncthreads();
    float r = sh[0];
    __syncthreads();
    return r;
}

// ---------------- sim fp32 -> fp16 (s2, overlapped with prologue) ----------------
__global__ void k_conv(const float* __restrict__ sim){
    size_t i = ((size_t)blockIdx.x * blockDim.x + threadIdx.x) * 2;
    const float4* in = (const float4*)sim;
    int4* outp = (int4*)g_simh;
    #pragma unroll
    for (int k = 0; k < 2; k++){
        size_t ii = i + k;
        float4 f0 = in[2*ii], f1 = in[2*ii+1];
        __half2 h0 = __floats2half2_rn(f0.x, f0.y);
        __half2 h1 = __floats2half2_rn(f0.z, f0.w);
        __half2 h2 = __floats2half2_rn(f1.x, f1.y);
        __half2 h3 = __floats2half2_rn(f1.z, f1.w);
        int4 o;
        o.x = *(int*)&h0; o.y = *(int*)&h1; o.z = *(int*)&h2; o.w = *(int*)&h3;
        outp[ii] = o;
    }
}

// ---------------- init ----------------
__global__ void k_init(const float* __restrict__ mem0){
    int i = blockIdx.x * blockDim.x + threadIdx.x;
    if (i < BB*TT) g_sp[i] = 0.f;
    if (i < BB*DMx) g_memA[i] = mem0[i];
}

// ---------------- M = Wk^T @ Wq ----------------
__global__ void k_Mpre(const float* __restrict__ Wk, const float* __restrict__ Wq){
    int bm = blockIdx.x & 15, bd = blockIdx.x >> 4;
    int d0 = bd*32, m0 = bm*32;
    __shared__ float sA[32*32];
    __shared__ float sB[32*32];
    float acc[4] = {0.f, 0.f, 0.f, 0.f};
    int tx = threadIdx.x & 31, ty = threadIdx.x >> 5;
    for (int a0 = 0; a0 < DAx; a0 += 32){
        __syncthreads();
        for (int i = threadIdx.x; i < 1024; i += 256){
            int ar = i >> 5, col = i & 31;
            sA[i] = Wk[(size_t)(a0+ar)*DUx + d0 + col];
            sB[i] = Wq[(size_t)(a0+ar)*DMx + m0 + col];
        }
        __syncthreads();
        #pragma unroll
        for (int aa = 0; aa < 32; aa++){
            float bv = sB[aa*32 + tx];
            #pragma unroll
            for (int r = 0; r < 4; r++)
                acc[r] += sA[aa*32 + ty + r*8] * bv;
        }
    }
    #pragma unroll
    for (int r = 0; r < 4; r++)
        g_M[(size_t)(d0 + ty + r*8)*DMx + m0 + tx] = acc[r];
}

// ---------------- W_comb = W_ih[:, :512] @ Wv ; 64x32 tiles, 8 accs ----------------
__global__ void k_Wcomb(const float* __restrict__ Wih, const float* __restrict__ Wv){
    // grid: 24 row-tiles (64 rows) x 16 col-tiles (32 cols) = 384 blocks, 256 threads
    int bc = blockIdx.x & 15, br = blockIdx.x >> 4;
    int r0 = br*64, c0 = bc*32;
    __shared__ float sA[32*65];   // sA[k][row], padded
    __shared__ float sB[32*32];   // sB[k][col]
    float acc[8] = {0,0,0,0,0,0,0,0};
    int tx = threadIdx.x & 31, ty = threadIdx.x >> 5;   // ty 0..7
    for (int k0 = 0; k0 < DUx; k0 += 32){
        __syncthreads();
        #pragma unroll
        for (int i = threadIdx.x; i < 2048; i += 256){
            int row = i >> 5, k = i & 31;
            sA[k*65 + row] = Wih[(size_t)(r0+row)*516 + k0 + k];
        }
        for (int i = threadIdx.x; i < 1024; i += 256){
            int k = i >> 5, col = i & 31;
            sB[k*32 + col] = Wv[(size_t)(k0+k)*DUx + c0 + col];
        }
        __syncthreads();
        #pragma unroll
        for (int kk = 0; kk < 32; kk++){
            float bv = sB[kk*32 + tx];
            #pragma unroll
            for (int r = 0; r < 8; r++)
                acc[r] += sA[kk*65 + ty + r*8] * bv;
        }
    }
    #pragma unroll
    for (int r = 0; r < 8; r++)
        g_Wc[(size_t)(r0 + ty + r*8)*DUx + c0 + tx] = acc[r];
}

// ---------------- gh[b,r] = W_hh[r,:]@mem[b,:] + b_hh[r]  (side stream) ----------------
__global__ void k_gh(const float* __restrict__ W_hh, const float* __restrict__ b_hh, int inB){
    const float* mem_in = inB ? g_memB : g_memA;
    __shared__ float4 s_m4[BB*DMx/4];
    for (int i = threadIdx.x; i < BB*DMx/4; i += 256)
        s_m4[i] = ((const float4*)mem_in)[i];
    __syncthreads();
    int w = threadIdx.x >> 5, lane = threadIdx.x & 31;
    int r = blockIdx.x * 8 + w;
    const float4* row = (const float4*)(W_hh + (size_t)r * DMx);
    float4 wr[4];
    #pragma unroll
    for (int c = 0; c < 4; c++) wr[c] = row[c*32 + lane];
    float bias = b_hh[r];
    #pragma unroll
    for (int b = 0; b < BB; b++){
        float a = 0.f;
        #pragma unroll
        for (int c = 0; c < 4; c++){
            float4 m4 = s_m4[b*128 + c*32 + lane];
            a += wr[c].x*m4.x + wr[c].y*m4.y + wr[c].z*m4.z + wr[c].w*m4.w;
        }
        a = warpSum(a);
        if (lane == 0) g_gh[b*1536 + r] = a + bias;
    }
}

// ---------------- gi_main[b,r] = Wc[r,:]@yu[b,:] + b_ih[r]  (side stream) ----------------
__global__ void k_gimain(const float* __restrict__ b_ih){
    __shared__ float4 s_y4[BB*DUx/4];
    for (int i = threadIdx.x; i < BB*DUx/4; i += 256)
        s_y4[i] = ((const float4*)g_yu)[i];
    __syncthreads();
    int w = threadIdx.x >> 5, lane = threadIdx.x & 31;
    int r = blockIdx.x * 8 + w;
    const float4* row = (const float4*)(g_Wc + (size_t)r * DUx);
    float4 wr[4];
    #pragma unroll
    for (int c = 0; c < 4; c++) wr[c] = row[c*32 + lane];
    float bias = b_ih[r];
    #pragma unroll
    for (int b = 0; b < BB; b++){
        float a = 0.f;
        #pragma unroll
        for (int c = 0; c < 4; c++){
            float4 m4 = s_y4[b*128 + c*32 + lane];
            a += wr[c].x*m4.x + wr[c].y*m4.y + wr[c].z*m4.z + wr[c].w*m4.w;
        }
        a = warpSum(a);
        if (lane == 0) g_gi[b*1536 + r] = a + bias;
    }
}

// ---------------- precompute: usq, sbias, u->fp16; 2 rows/warp ----------------
__global__ void k_pre(const float* __restrict__ u, const float* __restrict__ sf,
                      const float* __restrict__ w1, const float* __restrict__ b1,
                      const float* __restrict__ w2, const float* __restrict__ b2){
    int b  = blockIdx.x >> 7;
    int t0 = (blockIdx.x & 127) * 16;
    int w = threadIdx.x >> 5, lane = threadIdx.x & 31;
    int tA = t0 + w, tB = t0 + w + 8;
    int btA = b*TT + tA, btB = b*TT + tB;
    const float4* upA = (const float4*)(u + (size_t)btA * DUx);
    const float4* upB = (const float4*)(u + (size_t)btB * DUx);
    int4* uoA = (int4*)(g_uh + (size_t)btA * DUx);
    int4* uoB = (int4*)(g_uh + (size_t)btB * DUx);
    float accA = 0.f, accB = 0.f;
    #pragma unroll
    for (int c = 0; c < 2; c++){
        int idx = c*32 + lane;
        float4 a0 = upA[2*idx], a1 = upA[2*idx+1];
        float4 b0 = upB[2*idx], b1v = upB[2*idx+1];
        accA += a0.x*a0.x + a0.y*a0.y + a0.z*a0.z + a0.w*a0.w
              + a1.x*a1.x + a1.y*a1.y + a1.z*a1.z + a1.w*a1.w;
        accB += b0.x*b0.x + b0.y*b0.y + b0.z*b0.z + b0.w*b0.w
              + b1v.x*b1v.x + b1v.y*b1v.y + b1v.z*b1v.z + b1v.w*b1v.w;
        __half2 hA0 = __floats2half2_rn(a0.x, a0.y), hA1 = __floats2half2_rn(a0.z, a0.w);
        __half2 hA2 = __floats2half2_rn(a1.x, a1.y), hA3 = __floats2half2_rn(a1.z, a1.w);
        __half2 hB0 = __floats2half2_rn(b0.x, b0.y), hB1 = __floats2half2_rn(b0.z, b0.w);
        __half2 hB2 = __floats2half2_rn(b1v.x, b1v.y), hB3 = __floats2half2_rn(b1v.z, b1v.w);
        int4 oA, oB;
        oA.x = *(int*)&hA0; oA.y = *(int*)&hA1; oA.z = *(int*)&hA2; oA.w = *(int*)&hA3;
        oB.x = *(int*)&hB0; oB.y = *(int*)&hB1; oB.z = *(int*)&hB2; oB.w = *(int*)&hB3;
        uoA[idx] = oA; uoB[idx] = oB;
    }
    accA = warpSum(accA); accB = warpSum(accB);
    float dA0 = sf[btA*DFx + 8], dA1 = sf[btA*DFx + 9], dA2 = sf[btA*DFx + 10];
    float dB0 = sf[btB*DFx + 8], dB1 = sf[btB*DFx + 9], dB2 = sf[btB*DFx + 10];
    float sbA = 0.f, sbB = 0.f;
    #pragma unroll
    for (int k = 0; k < 8; k++){
        int a = lane + k*32;
        float w1a = w1[a*3+0], w1b = w1[a*3+1], w1c = w1[a*3+2], bb = b1[a], w2a = w2[a];
        float hA = w1a*dA0 + w1b*dA1 + w1c*dA2 + bb;
        float hB = w1a*dB0 + w1b*dB1 + w1c*dB2 + bb;
        hA = 0.5f * hA * (1.f + erff(hA * 0.70710678118654752f));
        hB = 0.5f * hB * (1.f + erff(hB * 0.70710678118654752f));
        sbA += hA * w2a; sbB += hB * w2a;
    }
    sbA = warpSum(sbA); sbB = warpSum(sbB);
    if (lane == 0){
        g_usq[btA] = accA; g_sbias[btA] = sbA + b2[0];
        g_usq[btB] = accB; g_sbias[btB] = sbB + b2[0];
    }
}

// ---------------- qk (prologue only; 128 blocks) ----------------
__global__ void k_qk(int inB){
    const float* mem_in = inB ? g_memB : g_memA;
    int b = blockIdx.x >> 4;
    int c = blockIdx.x & 15;
    __shared__ float4 s_m4[DMx/4];
    for (int i = threadIdx.x; i < DMx/4; i += 256)
        s_m4[i] = ((const float4*)(mem_in + b*DMx))[i];
    __syncthreads();
    int w = threadIdx.x >> 5, lane = threadIdx.x & 31;
    #pragma unroll
    for (int j = 0; j < 4; j++){
        int d = c*32 + w*4 + j;
        const float4* row = (const float4*)(g_M + (size_t)d * DMx);
        float acc = 0.f;
        #pragma unroll
        for (int cc = 0; cc < 4; cc++){
            int idx = cc*32 + lane;
            float4 a = row[idx], m4 = s_m4[idx];
            acc += a.x*m4.x + a.y*m4.y + a.z*m4.z + a.w*m4.w;
        }
        acc = warpSum(acc);
        if (lane == 0) g_qk[b*DUx + d] = acc;
    }
}

// ---------------- base = u·qk/16 + sbias; 2 rows/warp ----------------
__global__ void k_scores(){
    int b  = blockIdx.x >> 7;
    int t0 = (blockIdx.x & 127) * 16;
    __shared__ float2 s_qk2[DUx/2];
    for (int i = threadIdx.x; i < DUx/2; i += blockDim.x)
        s_qk2[i] = ((const float2*)(g_qk + b*DUx))[i];
    __syncthreads();
    int w = threadIdx.x >> 5, lane = threadIdx.x & 31;
    int btA = b*TT + t0 + w, btB = btA + 8;
    const int4* rA = (const int4*)(g_uh + (size_t)btA * DUx);
    const int4* rB = (const int4*)(g_uh + (size_t)btB * DUx);
    int4 hA0 = rA[lane], hA1 = rA[32+lane];
    int4 hB0 = rB[lane], hB1 = rB[32+lane];
    float accA = 0.f, accB = 0.f;
    {
        __half2* pA0 = (__half2*)&hA0; __half2* pA1 = (__half2*)&hA1;
        __half2* pB0 = (__half2*)&hB0; __half2* pB1 = (__half2*)&hB1;
        #pragma unroll
        for (int j = 0; j < 4; j++){
            float2 q0 = s_qk2[lane*4 + j];
            float2 q1 = s_qk2[(32+lane)*4 + j];
            float2 a0 = __half22float2(pA0[j]), a1 = __half22float2(pA1[j]);
            float2 b0 = __half22float2(pB0[j]), b1v = __half22float2(pB1[j]);
            accA += a0.x*q0.x + a0.y*q0.y + a1.x*q1.x + a1.y*q1.y;
            accB += b0.x*q0.x + b0.y*q0.y + b1v.x*q1.x + b1v.y*q1.y;
        }
    }
    accA = warpSum(accA); accB = warpSum(accB);
    if (lane == 0){
        g_base[btA] = accA * INV_SCALE + g_sbias[btA];
        g_base[btB] = accB * INV_SCALE + g_sbias[btB];
    }
}

// ---------------- softmax((base-sp)/temp) + overlap (fp16 sim); 2 rows/warp ----------------
__global__ void k_simmv_ov(const float* __restrict__ lt){
    int b  = blockIdx.x >> 7;
    int t0 = (blockIdx.x & 127) * 16;
    __shared__ float2 s_y2[TT/2];
    __shared__ float sh[32];
    float temp = fminf(fmaxf(expf(lt[0]), 0.1f), 10.f);
    float invT = 1.f / temp;
    float lv[8];
    float mloc = -INFINITY;
    #pragma unroll
    for (int k = 0; k < 8; k++){
        int j = threadIdx.x + k*256;
        lv[k] = (g_base[b*TT+j] - g_sp[b*TT+j]) * invT;
        mloc = fmaxf(mloc, lv[k]);
    }
    float m = blockMax(mloc, sh);
    float se = 0.f;
    #pragma unroll
    for (int k = 0; k < 8; k++){
        int j = threadIdx.x + k*256;
        float e = expf(lv[k] - m);
        ((float*)s_y2)[j] = e;
        se += e;
    }
    float S = blockSum(se, sh);
    float invS = 1.f / S;
    int w = threadIdx.x >> 5, lane = threadIdx.x & 31;
    int btA = b*TT + t0 + w, btB = btA + 8;
    const int4* rowA = (const int4*)(g_simh + (size_t)btA * TT);
    const int4* rowB = (const int4*)(g_simh + (size_t)btB * TT);
    float accA = 0.f, accB = 0.f;
    #pragma unroll
    for (int c = 0; c < 8; c++){
        int idx = c*32 + lane;
        int4 hA = rowA[idx], hB = rowB[idx];
        __half2* pA = (__half2*)&hA; __half2* pB = (__half2*)&hB;
        #pragma unroll
        for (int j = 0; j < 4; j++){
            float2 yv = s_y2[idx*4 + j];
            float2 sa = __half22float2(pA[j]);
            float2 sb = __half22float2(pB[j]);
            accA += sa.x*yv.x + sa.y*yv.y;
            accB += sb.x*yv.x + sb.y*yv.y;
        }
    }
    accA = warpSum(accA); accB = warpSum(accB);
    if (lane == 0){
        g_overlap[btA] = accA * invS;
        g_overlap[btB] = accB * invS;
    }
}

// ---------------- sp += sim @ y_final (side stream); 2 rows/warp ----------------
__global__ void k_simmv_sp(){
    int b  = blockIdx.x >> 7;
    int t0 = (blockIdx.x & 127) * 16;
    __shared__ float2 s_y2[TT/2];
    for (int i = threadIdx.x; i < TT/2; i += blockDim.x)
        s_y2[i] = ((const float2*)(g_y + b*TT))[i];
    __syncthreads();
    int w = threadIdx.x >> 5, lane = threadIdx.x & 31;
    int btA = b*TT + t0 + w, btB = btA + 8;
    const int4* rowA = (const int4*)(g_simh + (size_t)btA * TT);
    const int4* rowB = (const int4*)(g_simh + (size_t)btB * TT);
    float accA = 0.f, accB = 0.f;
    #pragma unroll
    for (int c = 0; c < 8; c++){
        int idx = c*32 + lane;
        int4 hA = rowA[idx], hB = rowB[idx];
        __half2* pA = (__half2*)&hA; __half2* pB = (__half2*)&hB;
        #pragma unroll
        for (int j = 0; j < 4; j++){
            float2 yv = s_y2[idx*4 + j];
            float2 sa = __half22float2(pA[j]);
            float2 sb = __half22float2(pB[j]);
            accA += sa.x*yv.x + sa.y*yv.y;
            accB += sb.x*yv.x + sb.y*yv.y;
        }
    }
    accA = warpSum(accA); accB = warpSum(accB);
    if (lane == 0){
        g_sp[btA] += accA;
        g_sp[btB] += accB;
    }
}

// ---------------- penalty + second softmax + scalar stats ----------------
__global__ void k_penalty(const float* __restrict__ lt){
    int b = blockIdx.x;
    int i0 = b*TT + threadIdx.x, i1 = i0 + 1024;
    __shared__ float sh[32];
    float temp = fminf(fmaxf(expf(lt[0]), 0.1f), 10.f);
    float invT = 1.f / temp;
    float o0 = g_overlap[i0], o1 = g_overlap[i1];
    float mo = blockMax(fmaxf(o0, o1), sh);
    mo = fmaxf(mo, EPSV);
    float invmo = 1.f / mo;
    float l0 = (g_base[i0] - g_sp[i0]) * invT - o0*invmo;
    float l1 = (g_base[i1] - g_sp[i1]) * invT - o1*invmo;
    float m = blockMax(fmaxf(l0, l1), sh);
    float e0 = expf(l0 - m), e1 = expf(l1 - m);
    float S = blockSum(e0 + e1, sh);
    float invS = 1.f / S;
    float y0 = e0*invS, y1 = e1*invS;
    g_y[i0] = y0; g_y[i1] = y1;
    float ysum = blockSum(y0 + y1, sh);
    float ys = fmaxf(ysum, EPSV);
    float invys = 1.f / ys;
    float yn0 = y0*invys, yn1 = y1*invys;
    float ent = blockSum(-yn0*logf(fmaxf(yn0, EPSV)) - yn1*logf(fmaxf(yn1, EPSV)), sh);
    float wsq = blockSum(y0*g_usq[i0] + y1*g_usq[i1], sh);
    if (threadIdx.x == 0){
        g_stat[b*8+0] = ys;
        g_stat[b*8+1] = ysum * (1.f/(float)TT);
        g_stat[b*8+2] = ent;
        g_stat[b*8+3] = wsq;
        g_stat[b*8+4] = 0.f;
    }
    if (threadIdx.x < DUx) g_yu[b*DUx + threadIdx.x] = 0.f;
}

// ---------------- yu = y @ u ----------------
__global__ void k_yu(){
    int b  = blockIdx.x >> 6;
    int t0 = (blockIdx.x & 63) * 32;
    __shared__ float s_y[32];
    if (threadIdx.x < 32) s_y[threadIdx.x] = g_y[b*TT + t0 + threadIdx.x];
    __syncthreads();
    float ax = 0.f, ay = 0.f;
    const __half2* up = (const __half2*)(g_uh + ((size_t)b*TT + t0) * DUx);
    #pragma unroll 8
    for (int i = 0; i < 32; i++){
        float yv = s_y[i];
        float2 v = __half22float2(up[i*256 + threadIdx.x]);
        ax += yv * v.x; ay += yv * v.y;
    }
    atomicAdd(&g_yu[b*DUx + 2*threadIdx.x],     ax);
    atomicAdd(&g_yu[b*DUx + 2*threadIdx.x + 1], ay);
}

// ---------------- spread + csq; 2 rows/warp ----------------
__global__ void k_dist(){
    int b  = blockIdx.x >> 7;
    int t0 = (blockIdx.x & 127) * 16;
    __shared__ float2 s_cen2[DUx/2];
    __shared__ float sh[32];
    float ys = g_stat[b*8+0];
    float invys = 1.f / ys;
    for (int i = threadIdx.x; i < DUx/2; i += 256){
        float2 c2 = ((const float2*)(g_yu + b*DUx))[i];
        s_cen2[i] = make_float2(c2.x*invys, c2.y*invys);
    }
    __syncthreads();
    int w = threadIdx.x >> 5, lane = threadIdx.x & 31;
    int btA = b*TT + t0 + w, btB = btA + 8;
    const int4* rowA = (const int4*)(g_uh + (size_t)btA * DUx);
    const int4* rowB = (const int4*)(g_uh + (size_t)btB * DUx);
    float accA = 0.f, accB = 0.f;
    #pragma unroll
    for (int c = 0; c < 2; c++){
        int idx = c*32 + lane;
        int4 hA = rowA[idx], hB = rowB[idx];
        __half2* pA = (__half2*)&hA; __half2* pB = (__half2*)&hB;
        #pragma unroll
        for (int j = 0; j < 4; j++){
            float2 cn = s_cen2[idx*4 + j];
            float2 uA = __half22float2(pA[j]);
            float2 uB = __half22float2(pB[j]);
            float dxA = uA.x - cn.x, dyA = uA.y - cn.y;
            float dxB = uB.x - cn.x, dyB = uB.y - cn.y;
            accA += dxA*dxA + dyA*dyA;
            accB += dxB*dxB + dyB*dyB;
        }
    }
    accA = warpSum(accA); accB = warpSum(accB);
    float part = (lane == 0) ? (g_y[btA]*sqrtf(accA) + g_y[btB]*sqrtf(accB)) : 0.f;
    float tot = blockSum(part, sh);
    if (threadIdx.x == 0) atomicAdd(&g_stat[b*8+4], tot);
    if ((blockIdx.x & 127) == 0){
        float2 c2 = s_cen2[threadIdx.x];
        float v = blockSum(c2.x*c2.x + c2.y*c2.y, sh);
        if (threadIdx.x == 0) g_stat[b*8+5] = v * ys * ys;   // csq = sum(yu^2)
    }
}

// ---------------- z = Wv @ yu -> out only (side stream) ----------------
__global__ void k_zx(const float* __restrict__ Wv, float* __restrict__ out, int stage){
    int b = blockIdx.x >> 3;
    int c = blockIdx.x & 7;
    __shared__ float4 s_yu4[DUx/4];
    for (int i = threadIdx.x; i < DUx/4; i += 256)
        s_yu4[i] = ((const float4*)(g_yu + b*DUx))[i];
    __syncthreads();
    int w = threadIdx.x >> 5, lane = threadIdx.x & 31;
    #pragma unroll
    for (int j = 0; j < 8; j++){
        int d = c*64 + w*8 + j;
        const float4* row = (const float4*)(Wv + (size_t)d * DUx);
        float acc = 0.f;
        #pragma unroll
        for (int cc = 0; cc < 4; cc++){
            int idx = cc*32 + lane;
            float4 a = row[idx], yv = s_yu4[idx];
            acc += a.x*yv.x + a.y*yv.y + a.z*yv.z + a.w*yv.w;
        }
        acc = warpSum(acc);
        if (lane == 0)
            out[((size_t)b*NSTAGE + stage)*DUx + d] = acc;
    }
}

// ---------------- fused GRU-finish + qk (128 blocks) ----------------
// Each block: recompute gates for its batch into smem (cheap), block c==0
// also writes mem_out; then compute its 32 qk rows from smem.
__global__ void k_gruqk(const float* __restrict__ Wih, int inB){
    const float* mem_in  = inB ? g_memB : g_memA;
    float*       mem_out = inB ? g_memA : g_memB;
    int b = blockIdx.x >> 4;
    int c = blockIdx.x & 15;
    __shared__ float4 s_m4[DMx/4];
    __shared__ float s_c[4];
    float* s_m = (float*)s_m4;
    if (threadIdx.x == 0){
        float ys = g_stat[b*8+0];
        s_c[0] = g_stat[b*8+1];
        s_c[1] = g_stat[b*8+2];
        s_c[2] = g_stat[b*8+4] / ys;
        s_c[3] = 2.f*(ys*g_stat[b*8+3] - g_stat[b*8+5]) / fmaxf(ys*ys, EPSV);
    }
    __syncthreads();
    #pragma unroll
    for (int jj = 0; jj < 2; jj++){
        int j = threadIdx.x + jj*256;
        float gi[3], gh[3];
        #pragma unroll
        for (int g = 0; g < 3; g++){
            int r = j + g*DMx;
            const float4 tl = *(const float4*)(Wih + (size_t)r * 516 + 512);
            gi[g] = g_gi[b*1536 + r]
                  + tl.x*s_c[0] + tl.y*s_c[1] + tl.z*s_c[2] + tl.w*s_c[3];
            gh[g] = g_gh[b*1536 + r];
        }
        float rg = 1.f / (1.f + expf(-(gi[0] + gh[0])));
        float zg = 1.f / (1.f + expf(-(gi[1] + gh[1])));
        float ng = tanhf(gi[2] + rg * gh[2]);
        float val = (1.f - zg) * ng + zg * mem_in[b*DMx + j];
        s_m[j] = val;
        if (c == 0) mem_out[b*DMx + j] = val;
    }
    __syncthreads();
    int w = threadIdx.x >> 5, lane = threadIdx.x & 31;
    #pragma unroll
    for (int j = 0; j < 4; j++){
        int d = c*32 + w*4 + j;
        const float4* row = (const float4*)(g_M + (size_t)d * DMx);
        float acc = 0.f;
        #pragma unroll
        for (int cc = 0; cc < 4; cc++){
            int idx = cc*32 + lane;
            float4 a = row[idx], m4 = s_m4[idx];
            acc += a.x*m4.x + a.y*m4.y + a.z*m4.z + a.w*m4.w;
        }
        acc = warpSum(acc);
        if (lane == 0) g_qk[b*DUx + d] = acc;
    }
}

// ---------------- launch ----------------
extern "C" void kernel_launch(void* const* d_in, const int* in_sizes, int n_in,
                              void* d_out, int out_size){
    const float* u    = (const float*)d_in[0];
    const float* sf   = (const float*)d_in[1];
    const float* sim  = (const float*)d_in[2];
    const float* mem0 = (const float*)d_in[3];
    const float* Wq   = (const float*)d_in[4];
    const float* Wk   = (const float*)d_in[5];
    const float* Wv   = (const float*)d_in[6];
    const float* sbw1 = (const float*)d_in[7];
    const float* sbb1 = (const float*)d_in[8];
    const float* sbw2 = (const float*)d_in[9];
    const float* sbb2 = (const float*)d_in[10];
    const float* lt   = (const float*)d_in[11];
    const float* Wih  = (const float*)d_in[12];
    const float* bih  = (const float*)d_in[13];
    const float* Whh  = (const float*)d_in[14];
    const float* bhh  = (const float*)d_in[15];
    float* out = (float*)d_out;

    static cudaStream_t s2 = nullptr, s3 = nullptr;
    static cudaEvent_t evR, evM, evC, evF[3], evJ[3], evY[4], evZ[4], evG[3], evGH[4], evGI[4];
    if (s2 == nullptr){
        cudaStreamCreateWithFlags(&s2, cudaStreamNonBlocking);
        cudaStreamCreateWithFlags(&s3, cudaStreamNonBlocking);
        cudaEventCreateWithFlags(&evR, cudaEventDisableTiming);
        cudaEventCreateWithFlags(&evM, cudaEventDisableTiming);
        cudaEventCreateWithFlags(&evC, cudaEventDisableTiming);
        for (int i = 0; i < 3; i++){
            cudaEventCreateWithFlags(&evF[i], cudaEventDisableTiming);
            cudaEventCreateWithFlags(&evJ[i], cudaEventDisableTiming);
            cudaEventCreateWithFlags(&evG[i], cudaEventDisableTiming);
        }
        for (int i = 0; i < 4; i++){
            cudaEventCreateWithFlags(&evY[i], cudaEventDisableTiming);
            cudaEventCreateWithFlags(&evZ[i], cudaEventDisableTiming);
            cudaEventCreateWithFlags(&evGH[i], cudaEventDisableTiming);
            cudaEventCreateWithFlags(&evGI[i], cudaEventDisableTiming);
        }
    }

    // prologue: s2 = sim conversion; s3 = init+Mpre+gh0; main = pre+qk+scores+Wcomb
    cudaEventRecord(evR, 0);
    cudaStreamWaitEvent(s2, evR, 0);
    cudaStreamWaitEvent(s3, evR, 0);
    k_conv<<<8192, 256, 0, s2>>>(sim);
    cudaEventRecord(evC, s2);
    k_init<<<64, 256, 0, s3>>>(mem0);
    k_Mpre<<<256, 256, 0, s3>>>(Wk, Wq);
    cudaEventRecord(evM, s3);                          // M + memA + sp=0 ready
    k_gh<<<192, 256, 0, s3>>>(Whh, bhh, 0);            // gh for stage 0
    cudaEventRecord(evGH[0], s3);
    k_pre<<<BB*TT/16, 256>>>(u, sf, sbw1, sbb1, sbw2, sbb2);
    cudaStreamWaitEvent(0, evM, 0);
    k_qk<<<BB*16, 256>>>(0);
    k_scores<<<BB*TT/16, 256>>>();
    k_Wcomb<<<384, 256>>>(Wih, Wv);                    // fills pre-ov0 bubble on main
    cudaStreamWaitEvent(0, evC, 0);                    // fp16 sim ready

    for (int s = 0; s < NSTAGE; s++){
        int inB = s & 1;
        if (s > 0){
            cudaStreamWaitEvent(0, evJ[s-1], 0);       // sp ready
            cudaStreamWaitEvent(0, evZ[s-1], 0);       // zx/gimain done before yu zeroed
        }
        k_simmv_ov<<<BB*TT/16, 256>>>(lt);             // softmax + fp16 overlap
        k_penalty<<<BB, 1024>>>(lt);
        if (s < NSTAGE - 1){
            cudaEventRecord(evF[s], 0);
            cudaStreamWaitEvent(s2, evF[s], 0);
            k_simmv_sp<<<BB*TT/16, 256, 0, s2>>>();
            cudaEventRecord(evJ[s], s2);
        }
        k_yu<<<BB*64, 256>>>();
        cudaEventRecord(evY[s], 0);
        cudaStreamWaitEvent(s3, evY[s], 0);
        if (s < NSTAGE - 1){
            k_gimain<<<192, 256, 0, s3>>>(bih);        // gi main matvec, parallel with dist
            cudaEventRecord(evGI[s], s3);
        }
        k_zx<<<BB*8, 256, 0, s3>>>(Wv, out, s);        // out only, off critical path
        cudaEventRecord(evZ[s], s3);
        if (s < NSTAGE - 1){
            k_dist<<<BB*TT/16, 256>>>();               // spread + csq
            cudaStreamWaitEvent(0, evGH[s], 0);
            cudaStreamWaitEvent(0, evGI[s], 0);
            k_gruqk<<<BB*16, 256>>>(Wih, inB);         // gates + qk fused
            cudaEventRecord(evG[s], 0);
            cudaStreamWaitEvent(s3, evG[s], 0);
            k_gh<<<192, 256, 0, s3>>>(Whh, bhh, (s+1) & 1);
            cudaEventRecord(evGH[s+1], s3);
            k_scores<<<BB*TT/16, 256>>>();
        }
    }
    cudaStreamWaitEvent(0, evZ[NSTAGE-1], 0);          // join final s3 branch
}

// round 16
// speedup vs baseline: 1.3859x; 1.0852x over previous
#include <cuda_runtime.h>
#include <cuda_fp16.h>
#include <math.h>

#define BB 8
#define TT 2048
#define DUx 512
#define DMx 512
#define DAx 256
#define DFx 12
#define NSTAGE 4
#define EPSV 1e-6f
#define INV_SCALE (1.0f/16.0f)

// ---------------- scratch (device globals; no allocation) ----------------
__device__ float g_usq[BB*TT];
__device__ float g_sbias[BB*TT];
__device__ float g_base[BB*TT];
__device__ float g_y[BB*TT];
__device__ float g_overlap[BB*TT];
__device__ float g_sp[BB*TT];
__device__ float g_yu[BB*DUx];
__device__ float g_memA[BB*DMx];
__device__ float g_memB[BB*DMx];
__device__ float g_qk[BB*DUx];
__device__ float g_stat[BB*8];     // [ys, coverage, entropy, wsq, spread, csq]
__device__ float g_M[DUx*DMx];     // Wk^T @ Wq
__device__ float g_Wc[3*DMx*DUx];  // W_ih[:, :512] @ Wv  (1536 x 512)
__device__ float g_gh[BB*3*DMx];   // W_hh @ mem + b_hh
__device__ float g_gi[BB*3*DMx];   // W_comb @ yu + b_ih

__device__ __half g_simh[(size_t)BB*TT*TT];   // 67 MB
__device__ __half g_uh[(size_t)BB*TT*DUx];    // 17 MB

// ---------------- reduction helpers ----------------
__device__ __forceinline__ float warpSum(float v){
    #pragma unroll
    for (int o = 16; o; o >>= 1) v += __shfl_xor_sync(0xffffffffu, v, o);
    return v;
}
__device__ __forceinline__ float warpMax(float v){
    #pragma unroll
    for (int o = 16; o; o >>= 1) v = fmaxf(v, __shfl_xor_sync(0xffffffffu, v, o));
    return v;
}
__device__ __forceinline__ float blockSum(float v, float* sh){
    int lane = threadIdx.x & 31, w = threadIdx.x >> 5;
    int nw = (blockDim.x + 31) >> 5;
    v = warpSum(v);
    if (lane == 0) sh[w] = v;
    __syncthreads();
    if (w == 0){
        float x = (lane < nw) ? sh[lane] : 0.f;
        x = warpSum(x);
        if (lane == 0) sh[0] = x;
    }
    __syncthreads();
    float r = sh[0];
    __syncthreads();
    return r;
}
__device__ __forceinline__ float blockMax(float v, float* sh){
    int lane = threadIdx.x & 31, w = threadIdx.x >> 5;
    int nw = (blockDim.x + 31) >> 5;
    v = warpMax(v);
    if (lane == 0) sh[w] = v;
    __syncthreads();
    if (w == 0){
        float x = (lane < nw) ? sh[lane] : -INFINITY;
        x = warpMax(x);
        if (lane == 0) sh[0] = x;
    }
    __syncthreads();
    float r = sh[0];
    __syncthreads();
    return r;
}

// ---------------- sim fp32 -> fp16 (s2, overlapped with prologue) ----------------
__global__ void k_conv(const float* __restrict__ sim){
    size_t i = ((size_t)blockIdx.x * blockDim.x + threadIdx.x) * 2;
    const float4* in = (const float4*)sim;
    int4* outp = (int4*)g_simh;
    #pragma unroll
    for (int k = 0; k < 2; k++){
        size_t ii = i + k;
        float4 f0 = in[2*ii], f1 = in[2*ii+1];
        __half2 h0 = __floats2half2_rn(f0.x, f0.y);
        __half2 h1 = __floats2half2_rn(f0.z, f0.w);
        __half2 h2 = __floats2half2_rn(f1.x, f1.y);
        __half2 h3 = __floats2half2_rn(f1.z, f1.w);
        int4 o;
        o.x = *(int*)&h0; o.y = *(int*)&h1; o.z = *(int*)&h2; o.w = *(int*)&h3;
        outp[ii] = o;
    }
}

// ---------------- init ----------------
__global__ void k_init(const float* __restrict__ mem0){
    int i = blockIdx.x * blockDim.x + threadIdx.x;
    if (i < BB*TT) g_sp[i] = 0.f;
    if (i < BB*DMx) g_memA[i] = mem0[i];
}

// ---------------- M = Wk^T @ Wq ----------------
__global__ void k_Mpre(const float* __restrict__ Wk, const float* __restrict__ Wq){
    int bm = blockIdx.x & 15, bd = blockIdx.x >> 4;
    int d0 = bd*32, m0 = bm*32;
    __shared__ float sA[32*32];
    __shared__ float sB[32*32];
    float acc[4] = {0.f, 0.f, 0.f, 0.f};
    int tx = threadIdx.x & 31, ty = threadIdx.x >> 5;
    for (int a0 = 0; a0 < DAx; a0 += 32){
        __syncthreads();
        for (int i = threadIdx.x; i < 1024; i += 256){
            int ar = i >> 5, col = i & 31;
            sA[i] = Wk[(size_t)(a0+ar)*DUx + d0 + col];
            sB[i] = Wq[(size_t)(a0+ar)*DMx + m0 + col];
        }
        __syncthreads();
        #pragma unroll
        for (int aa = 0; aa < 32; aa++){
            float bv = sB[aa*32 + tx];
            #pragma unroll
            for (int r = 0; r < 4; r++)
                acc[r] += sA[aa*32 + ty + r*8] * bv;
        }
    }
    #pragma unroll
    for (int r = 0; r < 4; r++)
        g_M[(size_t)(d0 + ty + r*8)*DMx + m0 + tx] = acc[r];
}

// ---------------- W_comb = W_ih[:, :512] @ Wv ; 64x32 tiles, 8 accs ----------------
__global__ void k_Wcomb(const float* __restrict__ Wih, const float* __restrict__ Wv){
    int bc = blockIdx.x & 15, br = blockIdx.x >> 4;   // 384 blocks
    int r0 = br*64, c0 = bc*32;
    __shared__ float sA[32*65];   // sA[k][row], padded
    __shared__ float sB[32*32];   // sB[k][col]
    float acc[8] = {0,0,0,0,0,0,0,0};
    int tx = threadIdx.x & 31, ty = threadIdx.x >> 5;
    for (int k0 = 0; k0 < DUx; k0 += 32){
        __syncthreads();
        #pragma unroll
        for (int i = threadIdx.x; i < 2048; i += 256){
            int row = i >> 5, k = i & 31;
            sA[k*65 + row] = Wih[(size_t)(r0+row)*516 + k0 + k];
        }
        for (int i = threadIdx.x; i < 1024; i += 256){
            int k = i >> 5, col = i & 31;
            sB[k*32 + col] = Wv[(size_t)(k0+k)*DUx + c0 + col];
        }
        __syncthreads();
        #pragma unroll
        for (int kk = 0; kk < 32; kk++){
            float bv = sB[kk*32 + tx];
            #pragma unroll
            for (int r = 0; r < 8; r++)
                acc[r] += sA[kk*65 + ty + r*8] * bv;
        }
    }
    #pragma unroll
    for (int r = 0; r < 8; r++)
        g_Wc[(size_t)(r0 + ty + r*8)*DUx + c0 + tx] = acc[r];
}

// ---------------- gh[b,r] = W_hh[r,:]@mem[b,:] + b_hh[r]  (side stream) ----------------
__global__ void k_gh(const float* __restrict__ W_hh, const float* __restrict__ b_hh, int inB){
    const float* mem_in = inB ? g_memB : g_memA;
    __shared__ float4 s_m4[BB*DMx/4];
    for (int i = threadIdx.x; i < BB*DMx/4; i += 256)
        s_m4[i] = ((const float4*)mem_in)[i];
    __syncthreads();
    int w = threadIdx.x >> 5, lane = threadIdx.x & 31;
    int r = blockIdx.x * 8 + w;
    const float4* row = (const float4*)(W_hh + (size_t)r * DMx);
    float4 wr[4];
    #pragma unroll
    for (int c = 0; c < 4; c++) wr[c] = row[c*32 + lane];
    float bias = b_hh[r];
    #pragma unroll
    for (int b = 0; b < BB; b++){
        float a = 0.f;
        #pragma unroll
        for (int c = 0; c < 4; c++){
            float4 m4 = s_m4[b*128 + c*32 + lane];
            a += wr[c].x*m4.x + wr[c].y*m4.y + wr[c].z*m4.z + wr[c].w*m4.w;
        }
        a = warpSum(a);
        if (lane == 0) g_gh[b*1536 + r] = a + bias;
    }
}

// ---------------- gi_main[b,r] = Wc[r,:]@yu[b,:] + b_ih[r]  (side stream) ----------------
__global__ void k_gimain(const float* __restrict__ b_ih){
    __shared__ float4 s_y4[BB*DUx/4];
    for (int i = threadIdx.x; i < BB*DUx/4; i += 256)
        s_y4[i] = ((const float4*)g_yu)[i];
    __syncthreads();
    int w = threadIdx.x >> 5, lane = threadIdx.x & 31;
    int r = blockIdx.x * 8 + w;
    const float4* row = (const float4*)(g_Wc + (size_t)r * DUx);
    float4 wr[4];
    #pragma unroll
    for (int c = 0; c < 4; c++) wr[c] = row[c*32 + lane];
    float bias = b_ih[r];
    #pragma unroll
    for (int b = 0; b < BB; b++){
        float a = 0.f;
        #pragma unroll
        for (int c = 0; c < 4; c++){
            float4 m4 = s_y4[b*128 + c*32 + lane];
            a += wr[c].x*m4.x + wr[c].y*m4.y + wr[c].z*m4.z + wr[c].w*m4.w;
        }
        a = warpSum(a);
        if (lane == 0) g_gi[b*1536 + r] = a + bias;
    }
}

// ---------------- precompute: usq, sbias, u->fp16; 2 rows/warp ----------------
__global__ void k_pre(const float* __restrict__ u, const float* __restrict__ sf,
                      const float* __restrict__ w1, const float* __restrict__ b1,
                      const float* __restrict__ w2, const float* __restrict__ b2){
    int b  = blockIdx.x >> 7;
    int t0 = (blockIdx.x & 127) * 16;
    int w = threadIdx.x >> 5, lane = threadIdx.x & 31;
    int tA = t0 + w, tB = t0 + w + 8;
    int btA = b*TT + tA, btB = b*TT + tB;
    const float4* upA = (const float4*)(u + (size_t)btA * DUx);
    const float4* upB = (const float4*)(u + (size_t)btB * DUx);
    int4* uoA = (int4*)(g_uh + (size_t)btA * DUx);
    int4* uoB = (int4*)(g_uh + (size_t)btB * DUx);
    float accA = 0.f, accB = 0.f;
    #pragma unroll
    for (int c = 0; c < 2; c++){
        int idx = c*32 + lane;
        float4 a0 = upA[2*idx], a1 = upA[2*idx+1];
        float4 b0 = upB[2*idx], b1v = upB[2*idx+1];
        accA += a0.x*a0.x + a0.y*a0.y + a0.z*a0.z + a0.w*a0.w
              + a1.x*a1.x + a1.y*a1.y + a1.z*a1.z + a1.w*a1.w;
        accB += b0.x*b0.x + b0.y*b0.y + b0.z*b0.z + b0.w*b0.w
              + b1v.x*b1v.x + b1v.y*b1v.y + b1v.z*b1v.z + b1v.w*b1v.w;
        __half2 hA0 = __floats2half2_rn(a0.x, a0.y), hA1 = __floats2half2_rn(a0.z, a0.w);
        __half2 hA2 = __floats2half2_rn(a1.x, a1.y), hA3 = __floats2half2_rn(a1.z, a1.w);
        __half2 hB0 = __floats2half2_rn(b0.x, b0.y), hB1 = __floats2half2_rn(b0.z, b0.w);
        __half2 hB2 = __floats2half2_rn(b1v.x, b1v.y), hB3 = __floats2half2_rn(b1v.z, b1v.w);
        int4 oA, oB;
        oA.x = *(int*)&hA0; oA.y = *(int*)&hA1; oA.z = *(int*)&hA2; oA.w = *(int*)&hA3;
        oB.x = *(int*)&hB0; oB.y = *(int*)&hB1; oB.z = *(int*)&hB2; oB.w = *(int*)&hB3;
        uoA[idx] = oA; uoB[idx] = oB;
    }
    accA = warpSum(accA); accB = warpSum(accB);
    float dA0 = sf[btA*DFx + 8], dA1 = sf[btA*DFx + 9], dA2 = sf[btA*DFx + 10];
    float dB0 = sf[btB*DFx + 8], dB1 = sf[btB*DFx + 9], dB2 = sf[btB*DFx + 10];
    float sbA = 0.f, sbB = 0.f;
    #pragma unroll
    for (int k = 0; k < 8; k++){
        int a = lane + k*32;
        float w1a = w1[a*3+0], w1b = w1[a*3+1], w1c = w1[a*3+2], bb = b1[a], w2a = w2[a];
        float hA = w1a*dA0 + w1b*dA1 + w1c*dA2 + bb;
        float hB = w1a*dB0 + w1b*dB1 + w1c*dB2 + bb;
        hA = 0.5f * hA * (1.f + erff(hA * 0.70710678118654752f));
        hB = 0.5f * hB * (1.f + erff(hB * 0.70710678118654752f));
        sbA += hA * w2a; sbB += hB * w2a;
    }
    sbA = warpSum(sbA); sbB = warpSum(sbB);
    if (lane == 0){
        g_usq[btA] = accA; g_sbias[btA] = sbA + b2[0];
        g_usq[btB] = accB; g_sbias[btB] = sbB + b2[0];
    }
}

// ---------------- qk[b,:] = M @ mem[b,:]  (128 blocks) ----------------
__global__ void k_qk(int inB){
    const float* mem_in = inB ? g_memB : g_memA;
    int b = blockIdx.x >> 4;
    int c = blockIdx.x & 15;
    __shared__ float4 s_m4[DMx/4];
    for (int i = threadIdx.x; i < DMx/4; i += 256)
        s_m4[i] = ((const float4*)(mem_in + b*DMx))[i];
    __syncthreads();
    int w = threadIdx.x >> 5, lane = threadIdx.x & 31;
    #pragma unroll
    for (int j = 0; j < 4; j++){
        int d = c*32 + w*4 + j;
        const float4* row = (const float4*)(g_M + (size_t)d * DMx);
        float acc = 0.f;
        #pragma unroll
        for (int cc = 0; cc < 4; cc++){
            int idx = cc*32 + lane;
            float4 a = row[idx], m4 = s_m4[idx];
            acc += a.x*m4.x + a.y*m4.y + a.z*m4.z + a.w*m4.w;
        }
        acc = warpSum(acc);
        if (lane == 0) g_qk[b*DUx + d] = acc;
    }
}

// ---------------- base = u·qk/16 + sbias; 2 rows/warp ----------------
__global__ void k_scores(){
    int b  = blockIdx.x >> 7;
    int t0 = (blockIdx.x & 127) * 16;
    __shared__ float2 s_qk2[DUx/2];
    for (int i = threadIdx.x; i < DUx/2; i += blockDim.x)
        s_qk2[i] = ((const float2*)(g_qk + b*DUx))[i];
    __syncthreads();
    int w = threadIdx.x >> 5, lane = threadIdx.x & 31;
    int btA = b*TT + t0 + w, btB = btA + 8;
    const int4* rA = (const int4*)(g_uh + (size_t)btA * DUx);
    const int4* rB = (const int4*)(g_uh + (size_t)btB * DUx);
    int4 hA0 = rA[lane], hA1 = rA[32+lane];
    int4 hB0 = rB[lane], hB1 = rB[32+lane];
    float accA = 0.f, accB = 0.f;
    {
        __half2* pA0 = (__half2*)&hA0; __half2* pA1 = (__half2*)&hA1;
        __half2* pB0 = (__half2*)&hB0; __half2* pB1 = (__half2*)&hB1;
        #pragma unroll
        for (int j = 0; j < 4; j++){
            float2 q0 = s_qk2[lane*4 + j];
            float2 q1 = s_qk2[(32+lane)*4 + j];
            float2 a0 = __half22float2(pA0[j]), a1 = __half22float2(pA1[j]);
            float2 b0 = __half22float2(pB0[j]), b1v = __half22float2(pB1[j]);
            accA += a0.x*q0.x + a0.y*q0.y + a1.x*q1.x + a1.y*q1.y;
            accB += b0.x*q0.x + b0.y*q0.y + b1v.x*q1.x + b1v.y*q1.y;
        }
    }
    accA = warpSum(accA); accB = warpSum(accB);
    if (lane == 0){
        g_base[btA] = accA * INV_SCALE + g_sbias[btA];
        g_base[btB] = accB * INV_SCALE + g_sbias[btB];
    }
}

// ---------------- softmax((base-sp)/temp) + overlap (fp16 sim); 2 rows/warp ----------------
__global__ void k_simmv_ov(const float* __restrict__ lt){
    int b  = blockIdx.x >> 7;
    int t0 = (blockIdx.x & 127) * 16;
    __shared__ float2 s_y2[TT/2];
    __shared__ float sh[32];
    float temp = fminf(fmaxf(expf(lt[0]), 0.1f), 10.f);
    float invT = 1.f / temp;
    float lv[8];
    float mloc = -INFINITY;
    #pragma unroll
    for (int k = 0; k < 8; k++){
        int j = threadIdx.x + k*256;
        lv[k] = (g_base[b*TT+j] - g_sp[b*TT+j]) * invT;
        mloc = fmaxf(mloc, lv[k]);
    }
    float m = blockMax(mloc, sh);
    float se = 0.f;
    #pragma unroll
    for (int k = 0; k < 8; k++){
        int j = threadIdx.x + k*256;
        float e = expf(lv[k] - m);
        ((float*)s_y2)[j] = e;
        se += e;
    }
    float S = blockSum(se, sh);
    float invS = 1.f / S;
    int w = threadIdx.x >> 5, lane = threadIdx.x & 31;
    int btA = b*TT + t0 + w, btB = btA + 8;
    const int4* rowA = (const int4*)(g_simh + (size_t)btA * TT);
    const int4* rowB = (const int4*)(g_simh + (size_t)btB * TT);
    float accA = 0.f, accB = 0.f;
    #pragma unroll
    for (int c = 0; c < 8; c++){
        int idx = c*32 + lane;
        int4 hA = rowA[idx], hB = rowB[idx];
        __half2* pA = (__half2*)&hA; __half2* pB = (__half2*)&hB;
        #pragma unroll
        for (int j = 0; j < 4; j++){
            float2 yv = s_y2[idx*4 + j];
            float2 sa = __half22float2(pA[j]);
            float2 sb = __half22float2(pB[j]);
            accA += sa.x*yv.x + sa.y*yv.y;
            accB += sb.x*yv.x + sb.y*yv.y;
        }
    }
    accA = warpSum(accA); accB = warpSum(accB);
    if (lane == 0){
        g_overlap[btA] = accA * invS;
        g_overlap[btB] = accB * invS;
    }
}

// ---------------- sp += sim @ y_final (side stream); 2 rows/warp ----------------
__global__ void k_simmv_sp(){
    int b  = blockIdx.x >> 7;
    int t0 = (blockIdx.x & 127) * 16;
    __shared__ float2 s_y2[TT/2];
    for (int i = threadIdx.x; i < TT/2; i += blockDim.x)
        s_y2[i] = ((const float2*)(g_y + b*TT))[i];
    __syncthreads();
    int w = threadIdx.x >> 5, lane = threadIdx.x & 31;
    int btA = b*TT + t0 + w, btB = btA + 8;
    const int4* rowA = (const int4*)(g_simh + (size_t)btA * TT);
    const int4* rowB = (const int4*)(g_simh + (size_t)btB * TT);
    float accA = 0.f, accB = 0.f;
    #pragma unroll
    for (int c = 0; c < 8; c++){
        int idx = c*32 + lane;
        int4 hA = rowA[idx], hB = rowB[idx];
        __half2* pA = (__half2*)&hA; __half2* pB = (__half2*)&hB;
        #pragma unroll
        for (int j = 0; j < 4; j++){
            float2 yv = s_y2[idx*4 + j];
            float2 sa = __half22float2(pA[j]);
            float2 sb = __half22float2(pB[j]);
            accA += sa.x*yv.x + sa.y*yv.y;
            accB += sb.x*yv.x + sb.y*yv.y;
        }
    }
    accA = warpSum(accA); accB = warpSum(accB);
    if (lane == 0){
        g_sp[btA] += accA;
        g_sp[btB] += accB;
    }
}

// ---------------- penalty + second softmax + scalar stats ----------------
__global__ void k_penalty(const float* __restrict__ lt){
    int b = blockIdx.x;
    int i0 = b*TT + threadIdx.x, i1 = i0 + 1024;
    __shared__ float sh[32];
    float temp = fminf(fmaxf(expf(lt[0]), 0.1f), 10.f);
    float invT = 1.f / temp;
    float o0 = g_overlap[i0], o1 = g_overlap[i1];
    float mo = blockMax(fmaxf(o0, o1), sh);
    mo = fmaxf(mo, EPSV);
    float invmo = 1.f / mo;
    float l0 = (g_base[i0] - g_sp[i0]) * invT - o0*invmo;
    float l1 = (g_base[i1] - g_sp[i1]) * invT - o1*invmo;
    float m = blockMax(fmaxf(l0, l1), sh);
    float e0 = expf(l0 - m), e1 = expf(l1 - m);
    float S = blockSum(e0 + e1, sh);
    float invS = 1.f / S;
    float y0 = e0*invS, y1 = e1*invS;
    g_y[i0] = y0; g_y[i1] = y1;
    float ysum = blockSum(y0 + y1, sh);
    float ys = fmaxf(ysum, EPSV);
    float invys = 1.f / ys;
    float yn0 = y0*invys, yn1 = y1*invys;
    float ent = blockSum(-yn0*logf(fmaxf(yn0, EPSV)) - yn1*logf(fmaxf(yn1, EPSV)), sh);
    float wsq = blockSum(y0*g_usq[i0] + y1*g_usq[i1], sh);
    if (threadIdx.x == 0){
        g_stat[b*8+0] = ys;
        g_stat[b*8+1] = ysum * (1.f/(float)TT);
        g_stat[b*8+2] = ent;
        g_stat[b*8+3] = wsq;
        g_stat[b*8+4] = 0.f;
    }
    if (threadIdx.x < DUx) g_yu[b*DUx + threadIdx.x] = 0.f;
}

// ---------------- yu = y @ u ----------------
__global__ void k_yu(){
    int b  = blockIdx.x >> 6;
    int t0 = (blockIdx.x & 63) * 32;
    __shared__ float s_y[32];
    if (threadIdx.x < 32) s_y[threadIdx.x] = g_y[b*TT + t0 + threadIdx.x];
    __syncthreads();
    float ax = 0.f, ay = 0.f;
    const __half2* up = (const __half2*)(g_uh + ((size_t)b*TT + t0) * DUx);
    #pragma unroll 8
    for (int i = 0; i < 32; i++){
        float yv = s_y[i];
        float2 v = __half22float2(up[i*256 + threadIdx.x]);
        ax += yv * v.x; ay += yv * v.y;
    }
    atomicAdd(&g_yu[b*DUx + 2*threadIdx.x],     ax);
    atomicAdd(&g_yu[b*DUx + 2*threadIdx.x + 1], ay);
}

// ---------------- spread + csq; 2 rows/warp ----------------
__global__ void k_dist(){
    int b  = blockIdx.x >> 7;
    int t0 = (blockIdx.x & 127) * 16;
    __shared__ float2 s_cen2[DUx/2];
    __shared__ float sh[32];
    float ys = g_stat[b*8+0];
    float invys = 1.f / ys;
    for (int i = threadIdx.x; i < DUx/2; i += 256){
        float2 c2 = ((const float2*)(g_yu + b*DUx))[i];
        s_cen2[i] = make_float2(c2.x*invys, c2.y*invys);
    }
    __syncthreads();
    int w = threadIdx.x >> 5, lane = threadIdx.x & 31;
    int btA = b*TT + t0 + w, btB = btA + 8;
    const int4* rowA = (const int4*)(g_uh + (size_t)btA * DUx);
    const int4* rowB = (const int4*)(g_uh + (size_t)btB * DUx);
    float accA = 0.f, accB = 0.f;
    #pragma unroll
    for (int c = 0; c < 2; c++){
        int idx = c*32 + lane;
        int4 hA = rowA[idx], hB = rowB[idx];
        __half2* pA = (__half2*)&hA; __half2* pB = (__half2*)&hB;
        #pragma unroll
        for (int j = 0; j < 4; j++){
            float2 cn = s_cen2[idx*4 + j];
            float2 uA = __half22float2(pA[j]);
            float2 uB = __half22float2(pB[j]);
            float dxA = uA.x - cn.x, dyA = uA.y - cn.y;
            float dxB = uB.x - cn.x, dyB = uB.y - cn.y;
            accA += dxA*dxA + dyA*dyA;
            accB += dxB*dxB + dyB*dyB;
        }
    }
    accA = warpSum(accA); accB = warpSum(accB);
    float part = (lane == 0) ? (g_y[btA]*sqrtf(accA) + g_y[btB]*sqrtf(accB)) : 0.f;
    float tot = blockSum(part, sh);
    if (threadIdx.x == 0) atomicAdd(&g_stat[b*8+4], tot);
    if ((blockIdx.x & 127) == 0){
        float2 c2 = s_cen2[threadIdx.x];
        float v = blockSum(c2.x*c2.x + c2.y*c2.y, sh);
        if (threadIdx.x == 0) g_stat[b*8+5] = v * ys * ys;   // csq = sum(yu^2)
    }
}

// ---------------- z = Wv @ yu -> out only (side stream) ----------------
__global__ void k_zx(const float* __restrict__ Wv, float* __restrict__ out, int stage){
    int b = blockIdx.x >> 3;
    int c = blockIdx.x & 7;
    __shared__ float4 s_yu4[DUx/4];
    for (int i = threadIdx.x; i < DUx/4; i += 256)
        s_yu4[i] = ((const float4*)(g_yu + b*DUx))[i];
    __syncthreads();
    int w = threadIdx.x >> 5, lane = threadIdx.x & 31;
    #pragma unroll
    for (int j = 0; j < 8; j++){
        int d = c*64 + w*8 + j;
        const float4* row = (const float4*)(Wv + (size_t)d * DUx);
        float acc = 0.f;
        #pragma unroll
        for (int cc = 0; cc < 4; cc++){
            int idx = cc*32 + lane;
            float4 a = row[idx], yv = s_yu4[idx];
            acc += a.x*yv.x + a.y*yv.y + a.z*yv.z + a.w*yv.w;
        }
        acc = warpSum(acc);
        if (lane == 0)
            out[((size_t)b*NSTAGE + stage)*DUx + d] = acc;
    }
}

// ---------------- GRU finish: tail + gates (tiny, critical path) ----------------
__global__ void k_grufin(const float* __restrict__ Wih, int inB){
    const float* mem_in  = inB ? g_memB : g_memA;
    float*       mem_out = inB ? g_memA : g_memB;
    int b = blockIdx.x;
    int j = threadIdx.x;         // 512 threads
    __shared__ float s_c[4];
    if (threadIdx.x == 0){
        float ys = g_stat[b*8+0];
        s_c[0] = g_stat[b*8+1];
        s_c[1] = g_stat[b*8+2];
        s_c[2] = g_stat[b*8+4] / ys;
        s_c[3] = 2.f*(ys*g_stat[b*8+3] - g_stat[b*8+5]) / fmaxf(ys*ys, EPSV);
    }
    __syncthreads();
    float gi[3], gh[3];
    #pragma unroll
    for (int g = 0; g < 3; g++){
        int r = j + g*DMx;
        const float4 tl = *(const float4*)(Wih + (size_t)r * 516 + 512);
        gi[g] = g_gi[b*1536 + r]
              + tl.x*s_c[0] + tl.y*s_c[1] + tl.z*s_c[2] + tl.w*s_c[3];
        gh[g] = g_gh[b*1536 + r];
    }
    float rg = 1.f / (1.f + expf(-(gi[0] + gh[0])));
    float zg = 1.f / (1.f + expf(-(gi[1] + gh[1])));
    float ng = tanhf(gi[2] + rg * gh[2]);
    mem_out[b*DMx + j] = (1.f - zg) * ng + zg * mem_in[b*DMx + j];
}

// ---------------- launch ----------------
extern "C" void kernel_launch(void* const* d_in, const int* in_sizes, int n_in,
                              void* d_out, int out_size){
    const float* u    = (const float*)d_in[0];
    const float* sf   = (const float*)d_in[1];
    const float* sim  = (const float*)d_in[2];
    const float* mem0 = (const float*)d_in[3];
    const float* Wq   = (const float*)d_in[4];
    const float* Wk   = (const float*)d_in[5];
    const float* Wv   = (const float*)d_in[6];
    const float* sbw1 = (const float*)d_in[7];
    const float* sbb1 = (const float*)d_in[8];
    const float* sbw2 = (const float*)d_in[9];
    const float* sbb2 = (const float*)d_in[10];
    const float* lt   = (const float*)d_in[11];
    const float* Wih  = (const float*)d_in[12];
    const float* bih  = (const float*)d_in[13];
    const float* Whh  = (const float*)d_in[14];
    const float* bhh  = (const float*)d_in[15];
    float* out = (float*)d_out;

    static cudaStream_t s2 = nullptr, s3 = nullptr;
    static cudaEvent_t evR, evM, evC, evF[3], evJ[3], evY[4], evZ[4], evG[3], evGH[4], evGI[4];
    if (s2 == nullptr){
        cudaStreamCreateWithFlags(&s2, cudaStreamNonBlocking);
        cudaStreamCreateWithFlags(&s3, cudaStreamNonBlocking);
        cudaEventCreateWithFlags(&evR, cudaEventDisableTiming);
        cudaEventCreateWithFlags(&evM, cudaEventDisableTiming);
        cudaEventCreateWithFlags(&evC, cudaEventDisableTiming);
        for (int i = 0; i < 3; i++){
            cudaEventCreateWithFlags(&evF[i], cudaEventDisableTiming);
            cudaEventCreateWithFlags(&evJ[i], cudaEventDisableTiming);
            cudaEventCreateWithFlags(&evG[i], cudaEventDisableTiming);
        }
        for (int i = 0; i < 4; i++){
            cudaEventCreateWithFlags(&evY[i], cudaEventDisableTiming);
            cudaEventCreateWithFlags(&evZ[i], cudaEventDisableTiming);
            cudaEventCreateWithFlags(&evGH[i], cudaEventDisableTiming);
            cudaEventCreateWithFlags(&evGI[i], cudaEventDisableTiming);
        }
    }

    // prologue (3 streams): s2 = sim conversion; s3 = init+Mpre+gh0+Wcomb; main = pre+qk+scores
    cudaEventRecord(evR, 0);
    cudaStreamWaitEvent(s2, evR, 0);
    cudaStreamWaitEvent(s3, evR, 0);
    k_conv<<<8192, 256, 0, s2>>>(sim);
    cudaEventRecord(evC, s2);
    k_init<<<64, 256, 0, s3>>>(mem0);
    k_Mpre<<<256, 256, 0, s3>>>(Wk, Wq);
    cudaEventRecord(evM, s3);                          // M + memA + sp=0 ready
    k_gh<<<192, 256, 0, s3>>>(Whh, bhh, 0);            // gh for stage 0
    cudaEventRecord(evGH[0], s3);
    k_Wcomb<<<384, 256, 0, s3>>>(Wih, Wv);             // Wc ready before any gimain (s3 order)
    k_pre<<<BB*TT/16, 256>>>(u, sf, sbw1, sbb1, sbw2, sbb2);
    cudaStreamWaitEvent(0, evM, 0);
    k_qk<<<BB*16, 256>>>(0);
    k_scores<<<BB*TT/16, 256>>>();
    cudaStreamWaitEvent(0, evC, 0);                    // fp16 sim ready

    for (int s = 0; s < NSTAGE; s++){
        int inB = s & 1;
        int lastS = (s == NSTAGE - 1);
        if (s > 0){
            cudaStreamWaitEvent(0, evJ[s-1], 0);       // sp ready
            cudaStreamWaitEvent(0, evZ[s-1], 0);       // zx/gimain done before yu zeroed
        }
        k_simmv_ov<<<BB*TT/16, 256>>>(lt);             // softmax + fp16 overlap
        k_penalty<<<BB, 1024>>>(lt);
        if (!lastS){
            cudaEventRecord(evF[s], 0);
            cudaStreamWaitEvent(s2, evF[s], 0);
            k_simmv_sp<<<BB*TT/16, 256, 0, s2>>>();
            cudaEventRecord(evJ[s], s2);
        }
        k_yu<<<BB*64, 256>>>();
        cudaEventRecord(evY[s], 0);
        cudaStreamWaitEvent(s3, evY[s], 0);
        if (!lastS){
            k_gimain<<<192, 256, 0, s3>>>(bih);        // gi main matvec, parallel with dist
            cudaEventRecord(evGI[s], s3);
        }
        k_zx<<<BB*8, 256, 0, s3>>>(Wv, out, s);        // out only, off critical path
        cudaEventRecord(evZ[s], s3);
        if (!lastS){
            k_dist<<<BB*TT/16, 256>>>();               // spread + csq (2 rows/warp)
            cudaStreamWaitEvent(0, evGH[s], 0);
            cudaStreamWaitEvent(0, evGI[s], 0);
            k_grufin<<<BB, 512>>>(Wih, inB);           // tiny: tail + gates
            cudaEventRecord(evG[s], 0);
            cudaStreamWaitEvent(s3, evG[s], 0);
            k_gh<<<192, 256, 0, s3>>>(Whh, bhh, (s+1) & 1);
            cudaEventRecord(evGH[s+1], s3);
            k_qk<<<BB*16, 256>>>((s+1) & 1);
            k_scores<<<BB*TT/16, 256>>>();
        }
    }
    cudaStreamWaitEvent(0, evZ[NSTAGE-1], 0);          // join final s3 branch
}

// round 17
// speedup vs baseline: 1.5305x; 1.1044x over previous
#include <cuda_runtime.h>
#include <cuda_fp16.h>
#include <math.h>

#define BB 8
#define TT 2048
#define DUx 512
#define DMx 512
#define DAx 256
#define DFx 12
#define NSTAGE 4
#define EPSV 1e-6f
#define INV_SCALE (1.0f/16.0f)

// ---------------- scratch (device globals; no allocation) ----------------
__device__ float g_usq[BB*TT];
__device__ float g_sbias[BB*TT];
__device__ float g_base[BB*TT];
__device__ float g_y[BB*TT];
__device__ float g_overlap[BB*TT];
__device__ float g_sp[BB*TT];
__device__ float g_yu[BB*DUx];
__device__ float g_memA[BB*DMx];
__device__ float g_memB[BB*DMx];
__device__ float g_qk[BB*DUx];
__device__ float g_stat[BB*8];     // [ys, coverage, entropy, wsq, spread, csq]
__device__ float g_M[DUx*DMx];     // Wk^T @ Wq
__device__ float g_Wc[3*DMx*DUx];  // W_ih[:, :512] @ Wv  (1536 x 512)
__device__ float g_gh[BB*3*DMx];   // W_hh @ mem + b_hh
__device__ float g_gi[BB*3*DMx];   // W_comb @ yu + b_ih

__device__ __half g_simh[(size_t)BB*TT*TT];   // 67 MB
__device__ __half g_uh[(size_t)BB*TT*DUx];    // 17 MB

// ---------------- reduction helpers ----------------
__device__ __forceinline__ float warpSum(float v){
    #pragma unroll
    for (int o = 16; o; o >>= 1) v += __shfl_xor_sync(0xffffffffu, v, o);
    return v;
}
__device__ __forceinline__ float warpMax(float v){
    #pragma unroll
    for (int o = 16; o; o >>= 1) v = fmaxf(v, __shfl_xor_sync(0xffffffffu, v, o));
    return v;
}
__device__ __forceinline__ float blockSum(float v, float* sh){
    int lane = threadIdx.x & 31, w = threadIdx.x >> 5;
    int nw = (blockDim.x + 31) >> 5;
    v = warpSum(v);
    if (lane == 0) sh[w] = v;
    __syncthreads();
    if (w == 0){
        float x = (lane < nw) ? sh[lane] : 0.f;
        x = warpSum(x);
        if (lane == 0) sh[0] = x;
    }
    __syncthreads();
    float r = sh[0];
    __syncthreads();
    return r;
}
__device__ __forceinline__ float blockMax(float v, float* sh){
    int lane = threadIdx.x & 31, w = threadIdx.x >> 5;
    int nw = (blockDim.x + 31) >> 5;
    v = warpMax(v);
    if (lane == 0) sh[w] = v;
    __syncthreads();
    if (w == 0){
        float x = (lane < nw) ? sh[lane] : -INFINITY;
        x = warpMax(x);
        if (lane == 0) sh[0] = x;
    }
    __syncthreads();
    float r = sh[0];
    __syncthreads();
    return r;
}

// ---------------- sim fp32 -> fp16 (s2, overlapped with prologue) ----------------
__global__ void k_conv(const float* __restrict__ sim){
    size_t i = ((size_t)blockIdx.x * blockDim.x + threadIdx.x) * 2;
    const float4* in = (const float4*)sim;
    int4* outp = (int4*)g_simh;
    #pragma unroll
    for (int k = 0; k < 2; k++){
        size_t ii = i + k;
        float4 f0 = in[2*ii], f1 = in[2*ii+1];
        __half2 h0 = __floats2half2_rn(f0.x, f0.y);
        __half2 h1 = __floats2half2_rn(f0.z, f0.w);
        __half2 h2 = __floats2half2_rn(f1.x, f1.y);
        __half2 h3 = __floats2half2_rn(f1.z, f1.w);
        int4 o;
        o.x = *(int*)&h0; o.y = *(int*)&h1; o.z = *(int*)&h2; o.w = *(int*)&h3;
        outp[ii] = o;
    }
}

// ---------------- init ----------------
__global__ void k_init(const float* __restrict__ mem0){
    int i = blockIdx.x * blockDim.x + threadIdx.x;
    if (i < BB*TT) g_sp[i] = 0.f;
    if (i < BB*DMx) g_memA[i] = mem0[i];
}

// ---------------- M = Wk^T @ Wq ----------------
__global__ void k_Mpre(const float* __restrict__ Wk, const float* __restrict__ Wq){
    int bm = blockIdx.x & 15, bd = blockIdx.x >> 4;
    int d0 = bd*32, m0 = bm*32;
    __shared__ float sA[32*32];
    __shared__ float sB[32*32];
    float acc[4] = {0.f, 0.f, 0.f, 0.f};
    int tx = threadIdx.x & 31, ty = threadIdx.x >> 5;
    for (int a0 = 0; a0 < DAx; a0 += 32){
        __syncthreads();
        for (int i = threadIdx.x; i < 1024; i += 256){
            int ar = i >> 5, col = i & 31;
            sA[i] = Wk[(size_t)(a0+ar)*DUx + d0 + col];
            sB[i] = Wq[(size_t)(a0+ar)*DMx + m0 + col];
        }
        __syncthreads();
        #pragma unroll
        for (int aa = 0; aa < 32; aa++){
            float bv = sB[aa*32 + tx];
            #pragma unroll
            for (int r = 0; r < 4; r++)
                acc[r] += sA[aa*32 + ty + r*8] * bv;
        }
    }
    #pragma unroll
    for (int r = 0; r < 4; r++)
        g_M[(size_t)(d0 + ty + r*8)*DMx + m0 + tx] = acc[r];
}

// ---------------- W_comb = W_ih[:, :512] @ Wv  (R12 version, 768 blocks) ----------------
__global__ void k_Wcomb(const float* __restrict__ Wih, const float* __restrict__ Wv){
    int bc = blockIdx.x & 15, br = blockIdx.x >> 4;
    int r0 = br*32, c0 = bc*32;
    __shared__ float sA[32*32];
    __shared__ float sB[32*32];
    float acc[4] = {0.f, 0.f, 0.f, 0.f};
    int tx = threadIdx.x & 31, ty = threadIdx.x >> 5;
    for (int k0 = 0; k0 < DUx; k0 += 32){
        __syncthreads();
        for (int i = threadIdx.x; i < 1024; i += 256){
            int ar = i >> 5, col = i & 31;
            sA[i] = Wih[(size_t)(r0+ar)*516 + k0 + col];
            sB[i] = Wv[(size_t)(k0+ar)*DUx + c0 + col];
        }
        __syncthreads();
        #pragma unroll
        for (int kk = 0; kk < 32; kk++){
            float bv = sB[kk*32 + tx];
            #pragma unroll
            for (int r = 0; r < 4; r++)
                acc[r] += sA[(ty + r*8)*32 + kk] * bv;
        }
    }
    #pragma unroll
    for (int r = 0; r < 4; r++)
        g_Wc[(size_t)(r0 + ty + r*8)*DUx + c0 + tx] = acc[r];
}

// ---------------- gh[b,r] = W_hh[r,:]@mem[b,:] + b_hh[r]  (side stream) ----------------
__global__ void k_gh(const float* __restrict__ W_hh, const float* __restrict__ b_hh, int inB){
    const float* mem_in = inB ? g_memB : g_memA;
    __shared__ float4 s_m4[BB*DMx/4];
    for (int i = threadIdx.x; i < BB*DMx/4; i += 256)
        s_m4[i] = ((const float4*)mem_in)[i];
    __syncthreads();
    int w = threadIdx.x >> 5, lane = threadIdx.x & 31;
    int r = blockIdx.x * 8 + w;
    const float4* row = (const float4*)(W_hh + (size_t)r * DMx);
    float4 wr[4];
    #pragma unroll
    for (int c = 0; c < 4; c++) wr[c] = row[c*32 + lane];
    float bias = b_hh[r];
    #pragma unroll
    for (int b = 0; b < BB; b++){
        float a = 0.f;
        #pragma unroll
        for (int c = 0; c < 4; c++){
            float4 m4 = s_m4[b*128 + c*32 + lane];
            a += wr[c].x*m4.x + wr[c].y*m4.y + wr[c].z*m4.z + wr[c].w*m4.w;
        }
        a = warpSum(a);
        if (lane == 0) g_gh[b*1536 + r] = a + bias;
    }
}

// ---------------- gi_main[b,r] = Wc[r,:]@yu[b,:] + b_ih[r]  (side stream) ----------------
__global__ void k_gimain(const float* __restrict__ b_ih){
    __shared__ float4 s_y4[BB*DUx/4];
    for (int i = threadIdx.x; i < BB*DUx/4; i += 256)
        s_y4[i] = ((const float4*)g_yu)[i];
    __syncthreads();
    int w = threadIdx.x >> 5, lane = threadIdx.x & 31;
    int r = blockIdx.x * 8 + w;
    const float4* row = (const float4*)(g_Wc + (size_t)r * DUx);
    float4 wr[4];
    #pragma unroll
    for (int c = 0; c < 4; c++) wr[c] = row[c*32 + lane];
    float bias = b_ih[r];
    #pragma unroll
    for (int b = 0; b < BB; b++){
        float a = 0.f;
        #pragma unroll
        for (int c = 0; c < 4; c++){
            float4 m4 = s_y4[b*128 + c*32 + lane];
            a += wr[c].x*m4.x + wr[c].y*m4.y + wr[c].z*m4.z + wr[c].w*m4.w;
        }
        a = warpSum(a);
        if (lane == 0) g_gi[b*1536 + r] = a + bias;
    }
}

// ---------------- precompute: usq, sbias, u->fp16; 2 rows/warp ----------------
__global__ void k_pre(const float* __restrict__ u, const float* __restrict__ sf,
                      const float* __restrict__ w1, const float* __restrict__ b1,
                      const float* __restrict__ w2, const float* __restrict__ b2){
    int b  = blockIdx.x >> 7;
    int t0 = (blockIdx.x & 127) * 16;
    int w = threadIdx.x >> 5, lane = threadIdx.x & 31;
    int tA = t0 + w, tB = t0 + w + 8;
    int btA = b*TT + tA, btB = b*TT + tB;
    const float4* upA = (const float4*)(u + (size_t)btA * DUx);
    const float4* upB = (const float4*)(u + (size_t)btB * DUx);
    int4* uoA = (int4*)(g_uh + (size_t)btA * DUx);
    int4* uoB = (int4*)(g_uh + (size_t)btB * DUx);
    float accA = 0.f, accB = 0.f;
    #pragma unroll
    for (int c = 0; c < 2; c++){
        int idx = c*32 + lane;
        float4 a0 = upA[2*idx], a1 = upA[2*idx+1];
        float4 b0 = upB[2*idx], b1v = upB[2*idx+1];
        accA += a0.x*a0.x + a0.y*a0.y + a0.z*a0.z + a0.w*a0.w
              + a1.x*a1.x + a1.y*a1.y + a1.z*a1.z + a1.w*a1.w;
        accB += b0.x*b0.x + b0.y*b0.y + b0.z*b0.z + b0.w*b0.w
              + b1v.x*b1v.x + b1v.y*b1v.y + b1v.z*b1v.z + b1v.w*b1v.w;
        __half2 hA0 = __floats2half2_rn(a0.x, a0.y), hA1 = __floats2half2_rn(a0.z, a0.w);
        __half2 hA2 = __floats2half2_rn(a1.x, a1.y), hA3 = __floats2half2_rn(a1.z, a1.w);
        __half2 hB0 = __floats2half2_rn(b0.x, b0.y), hB1 = __floats2half2_rn(b0.z, b0.w);
        __half2 hB2 = __floats2half2_rn(b1v.x, b1v.y), hB3 = __floats2half2_rn(b1v.z, b1v.w);
        int4 oA, oB;
        oA.x = *(int*)&hA0; oA.y = *(int*)&hA1; oA.z = *(int*)&hA2; oA.w = *(int*)&hA3;
        oB.x = *(int*)&hB0; oB.y = *(int*)&hB1; oB.z = *(int*)&hB2; oB.w = *(int*)&hB3;
        uoA[idx] = oA; uoB[idx] = oB;
    }
    accA = warpSum(accA); accB = warpSum(accB);
    float dA0 = sf[btA*DFx + 8], dA1 = sf[btA*DFx + 9], dA2 = sf[btA*DFx + 10];
    float dB0 = sf[btB*DFx + 8], dB1 = sf[btB*DFx + 9], dB2 = sf[btB*DFx + 10];
    float sbA = 0.f, sbB = 0.f;
    #pragma unroll
    for (int k = 0; k < 8; k++){
        int a = lane + k*32;
        float w1a = w1[a*3+0], w1b = w1[a*3+1], w1c = w1[a*3+2], bb = b1[a], w2a = w2[a];
        float hA = w1a*dA0 + w1b*dA1 + w1c*dA2 + bb;
        float hB = w1a*dB0 + w1b*dB1 + w1c*dB2 + bb;
        hA = 0.5f * hA * (1.f + erff(hA * 0.70710678118654752f));
        hB = 0.5f * hB * (1.f + erff(hB * 0.70710678118654752f));
        sbA += hA * w2a; sbB += hB * w2a;
    }
    sbA = warpSum(sbA); sbB = warpSum(sbB);
    if (lane == 0){
        g_usq[btA] = accA; g_sbias[btA] = sbA + b2[0];
        g_usq[btB] = accB; g_sbias[btB] = sbB + b2[0];
    }
}

// ---------------- qk[b,:] = M @ mem[b,:]  (128 blocks) ----------------
__global__ void k_qk(int inB){
    const float* mem_in = inB ? g_memB : g_memA;
    int b = blockIdx.x >> 4;
    int c = blockIdx.x & 15;
    __shared__ float4 s_m4[DMx/4];
    for (int i = threadIdx.x; i < DMx/4; i += 256)
        s_m4[i] = ((const float4*)(mem_in + b*DMx))[i];
    __syncthreads();
    int w = threadIdx.x >> 5, lane = threadIdx.x & 31;
    #pragma unroll
    for (int j = 0; j < 4; j++){
        int d = c*32 + w*4 + j;
        const float4* row = (const float4*)(g_M + (size_t)d * DMx);
        float acc = 0.f;
        #pragma unroll
        for (int cc = 0; cc < 4; cc++){
            int idx = cc*32 + lane;
            float4 a = row[idx], m4 = s_m4[idx];
            acc += a.x*m4.x + a.y*m4.y + a.z*m4.z + a.w*m4.w;
        }
        acc = warpSum(acc);
        if (lane == 0) g_qk[b*DUx + d] = acc;
    }
}

// ---------------- base = u·qk/16 + sbias; 2 rows/warp ----------------
__global__ void k_scores(){
    int b  = blockIdx.x >> 7;
    int t0 = (blockIdx.x & 127) * 16;
    __shared__ float2 s_qk2[DUx/2];
    for (int i = threadIdx.x; i < DUx/2; i += blockDim.x)
        s_qk2[i] = ((const float2*)(g_qk + b*DUx))[i];
    __syncthreads();
    int w = threadIdx.x >> 5, lane = threadIdx.x & 31;
    int btA = b*TT + t0 + w, btB = btA + 8;
    const int4* rA = (const int4*)(g_uh + (size_t)btA * DUx);
    const int4* rB = (const int4*)(g_uh + (size_t)btB * DUx);
    int4 hA0 = rA[lane], hA1 = rA[32+lane];
    int4 hB0 = rB[lane], hB1 = rB[32+lane];
    float accA = 0.f, accB = 0.f;
    {
        __half2* pA0 = (__half2*)&hA0; __half2* pA1 = (__half2*)&hA1;
        __half2* pB0 = (__half2*)&hB0; __half2* pB1 = (__half2*)&hB1;
        #pragma unroll
        for (int j = 0; j < 4; j++){
            float2 q0 = s_qk2[lane*4 + j];
            float2 q1 = s_qk2[(32+lane)*4 + j];
            float2 a0 = __half22float2(pA0[j]), a1 = __half22float2(pA1[j]);
            float2 b0 = __half22float2(pB0[j]), b1v = __half22float2(pB1[j]);
            accA += a0.x*q0.x + a0.y*q0.y + a1.x*q1.x + a1.y*q1.y;
            accB += b0.x*q0.x + b0.y*q0.y + b1v.x*q1.x + b1v.y*q1.y;
        }
    }
    accA = warpSum(accA); accB = warpSum(accB);
    if (lane == 0){
        g_base[btA] = accA * INV_SCALE + g_sbias[btA];
        g_base[btB] = accB * INV_SCALE + g_sbias[btB];
    }
}

// ---------------- softmax((base-sp)/temp) + overlap (fp16 sim); 2 rows/warp ----------------
__global__ void k_simmv_ov(const float* __restrict__ lt){
    int b  = blockIdx.x >> 7;
    int t0 = (blockIdx.x & 127) * 16;
    __shared__ float2 s_y2[TT/2];
    __shared__ float sh[32];
    float temp = fminf(fmaxf(expf(lt[0]), 0.1f), 10.f);
    float invT = 1.f / temp;
    float lv[8];
    float mloc = -INFINITY;
    #pragma unroll
    for (int k = 0; k < 8; k++){
        int j = threadIdx.x + k*256;
        lv[k] = (g_base[b*TT+j] - g_sp[b*TT+j]) * invT;
        mloc = fmaxf(mloc, lv[k]);
    }
    float m = blockMax(mloc, sh);
    float se = 0.f;
    #pragma unroll
    for (int k = 0; k < 8; k++){
        int j = threadIdx.x + k*256;
        float e = expf(lv[k] - m);
        ((float*)s_y2)[j] = e;
        se += e;
    }
    float S = blockSum(se, sh);
    float invS = 1.f / S;
    int w = threadIdx.x >> 5, lane = threadIdx.x & 31;
    int btA = b*TT + t0 + w, btB = btA + 8;
    const int4* rowA = (const int4*)(g_simh + (size_t)btA * TT);
    const int4* rowB = (const int4*)(g_simh + (size_t)btB * TT);
    float accA = 0.f, accB = 0.f;
    #pragma unroll
    for (int c = 0; c < 8; c++){
        int idx = c*32 + lane;
        int4 hA = rowA[idx], hB = rowB[idx];
        __half2* pA = (__half2*)&hA; __half2* pB = (__half2*)&hB;
        #pragma unroll
        for (int j = 0; j < 4; j++){
            float2 yv = s_y2[idx*4 + j];
            float2 sa = __half22float2(pA[j]);
            float2 sb = __half22float2(pB[j]);
            accA += sa.x*yv.x + sa.y*yv.y;
            accB += sb.x*yv.x + sb.y*yv.y;
        }
    }
    accA = warpSum(accA); accB = warpSum(accB);
    if (lane == 0){
        g_overlap[btA] = accA * invS;
        g_overlap[btB] = accB * invS;
    }
}

// ---------------- sp += sim @ y_final (side stream); 2 rows/warp ----------------
__global__ void k_simmv_sp(){
    int b  = blockIdx.x >> 7;
    int t0 = (blockIdx.x & 127) * 16;
    __shared__ float2 s_y2[TT/2];
    for (int i = threadIdx.x; i < TT/2; i += blockDim.x)
        s_y2[i] = ((const float2*)(g_y + b*TT))[i];
    __syncthreads();
    int w = threadIdx.x >> 5, lane = threadIdx.x & 31;
    int btA = b*TT + t0 + w, btB = btA + 8;
    const int4* rowA = (const int4*)(g_simh + (size_t)btA * TT);
    const int4* rowB = (const int4*)(g_simh + (size_t)btB * TT);
    float accA = 0.f, accB = 0.f;
    #pragma unroll
    for (int c = 0; c < 8; c++){
        int idx = c*32 + lane;
        int4 hA = rowA[idx], hB = rowB[idx];
        __half2* pA = (__half2*)&hA; __half2* pB = (__half2*)&hB;
        #pragma unroll
        for (int j = 0; j < 4; j++){
            float2 yv = s_y2[idx*4 + j];
            float2 sa = __half22float2(pA[j]);
            float2 sb = __half22float2(pB[j]);
            accA += sa.x*yv.x + sa.y*yv.y;
            accB += sb.x*yv.x + sb.y*yv.y;
        }
    }
    accA = warpSum(accA); accB = warpSum(accB);
    if (lane == 0){
        g_sp[btA] += accA;
        g_sp[btB] += accB;
    }
}

// ---------------- penalty + second softmax + scalar stats ----------------
__global__ void k_penalty(const float* __restrict__ lt){
    int b = blockIdx.x;
    int i0 = b*TT + threadIdx.x, i1 = i0 + 1024;
    __shared__ float sh[32];
    float temp = fminf(fmaxf(expf(lt[0]), 0.1f), 10.f);
    float invT = 1.f / temp;
    float o0 = g_overlap[i0], o1 = g_overlap[i1];
    float mo = blockMax(fmaxf(o0, o1), sh);
    mo = fmaxf(mo, EPSV);
    float invmo = 1.f / mo;
    float l0 = (g_base[i0] - g_sp[i0]) * invT - o0*invmo;
    float l1 = (g_base[i1] - g_sp[i1]) * invT - o1*invmo;
    float m = blockMax(fmaxf(l0, l1), sh);
    float e0 = expf(l0 - m), e1 = expf(l1 - m);
    float S = blockSum(e0 + e1, sh);
    float invS = 1.f / S;
    float y0 = e0*invS, y1 = e1*invS;
    g_y[i0] = y0; g_y[i1] = y1;
    float ysum = blockSum(y0 + y1, sh);
    float ys = fmaxf(ysum, EPSV);
    float invys = 1.f / ys;
    float yn0 = y0*invys, yn1 = y1*invys;
    float ent = blockSum(-yn0*logf(fmaxf(yn0, EPSV)) - yn1*logf(fmaxf(yn1, EPSV)), sh);
    float wsq = blockSum(y0*g_usq[i0] + y1*g_usq[i1], sh);
    if (threadIdx.x == 0){
        g_stat[b*8+0] = ys;
        g_stat[b*8+1] = ysum * (1.f/(float)TT);
        g_stat[b*8+2] = ent;
        g_stat[b*8+3] = wsq;
        g_stat[b*8+4] = 0.f;
    }
    if (threadIdx.x < DUx) g_yu[b*DUx + threadIdx.x] = 0.f;
}

// ---------------- yu = y @ u ----------------
__global__ void k_yu(){
    int b  = blockIdx.x >> 6;
    int t0 = (blockIdx.x & 63) * 32;
    __shared__ float s_y[32];
    if (threadIdx.x < 32) s_y[threadIdx.x] = g_y[b*TT + t0 + threadIdx.x];
    __syncthreads();
    float ax = 0.f, ay = 0.f;
    const __half2* up = (const __half2*)(g_uh + ((size_t)b*TT + t0) * DUx);
    #pragma unroll 8
    for (int i = 0; i < 32; i++){
        float yv = s_y[i];
        float2 v = __half22float2(up[i*256 + threadIdx.x]);
        ax += yv * v.x; ay += yv * v.y;
    }
    atomicAdd(&g_yu[b*DUx + 2*threadIdx.x],     ax);
    atomicAdd(&g_yu[b*DUx + 2*threadIdx.x + 1], ay);
}

// ---------------- spread + csq; 2 rows/warp ----------------
__global__ void k_dist(){
    int b  = blockIdx.x >> 7;
    int t0 = (blockIdx.x & 127) * 16;
    __shared__ float2 s_cen2[DUx/2];
    __shared__ float sh[32];
    float ys = g_stat[b*8+0];
    float invys = 1.f / ys;
    for (int i = threadIdx.x; i < DUx/2; i += 256){
        float2 c2 = ((const float2*)(g_yu + b*DUx))[i];
        s_cen2[i] = make_float2(c2.x*invys, c2.y*invys);
    }
    __syncthreads();
    int w = threadIdx.x >> 5, lane = threadIdx.x & 31;
    int btA = b*TT + t0 + w, btB = btA + 8;
    const int4* rowA = (const int4*)(g_uh + (size_t)btA * DUx);
    const int4* rowB = (const int4*)(g_uh + (size_t)btB * DUx);
    float accA = 0.f, accB = 0.f;
    #pragma unroll
    for (int c = 0; c < 2; c++){
        int idx = c*32 + lane;
        int4 hA = rowA[idx], hB = rowB[idx];
        __half2* pA = (__half2*)&hA; __half2* pB = (__half2*)&hB;
        #pragma unroll
        for (int j = 0; j < 4; j++){
            float2 cn = s_cen2[idx*4 + j];
            float2 uA = __half22float2(pA[j]);
            float2 uB = __half22float2(pB[j]);
            float dxA = uA.x - cn.x, dyA = uA.y - cn.y;
            float dxB = uB.x - cn.x, dyB = uB.y - cn.y;
            accA += dxA*dxA + dyA*dyA;
            accB += dxB*dxB + dyB*dyB;
        }
    }
    accA = warpSum(accA); accB = warpSum(accB);
    float part = (lane == 0) ? (g_y[btA]*sqrtf(accA) + g_y[btB]*sqrtf(accB)) : 0.f;
    float tot = blockSum(part, sh);
    if (threadIdx.x == 0) atomicAdd(&g_stat[b*8+4], tot);
    if ((blockIdx.x & 127) == 0){
        float2 c2 = s_cen2[threadIdx.x];
        float v = blockSum(c2.x*c2.x + c2.y*c2.y, sh);
        if (threadIdx.x == 0) g_stat[b*8+5] = v * ys * ys;   // csq = sum(yu^2)
    }
}

// ---------------- z = Wv @ yu -> out only (side stream) ----------------
__global__ void k_zx(const float* __restrict__ Wv, float* __restrict__ out, int stage){
    int b = blockIdx.x >> 3;
    int c = blockIdx.x & 7;
    __shared__ float4 s_yu4[DUx/4];
    for (int i = threadIdx.x; i < DUx/4; i += 256)
        s_yu4[i] = ((const float4*)(g_yu + b*DUx))[i];
    __syncthreads();
    int w = threadIdx.x >> 5, lane = threadIdx.x & 31;
    #pragma unroll
    for (int j = 0; j < 8; j++){
        int d = c*64 + w*8 + j;
        const float4* row = (const float4*)(Wv + (size_t)d * DUx);
        float acc = 0.f;
        #pragma unroll
        for (int cc = 0; cc < 4; cc++){
            int idx = cc*32 + lane;
            float4 a = row[idx], yv = s_yu4[idx];
            acc += a.x*yv.x + a.y*yv.y + a.z*yv.z + a.w*yv.w;
        }
        acc = warpSum(acc);
        if (lane == 0)
            out[((size_t)b*NSTAGE + stage)*DUx + d] = acc;
    }
}

// ---------------- GRU finish: tail + gates (tiny, critical path) ----------------
__global__ void k_grufin(const float* __restrict__ Wih, int inB){
    const float* mem_in  = inB ? g_memB : g_memA;
    float*       mem_out = inB ? g_memA : g_memB;
    int b = blockIdx.x;
    int j = threadIdx.x;         // 512 threads
    __shared__ float s_c[4];
    if (threadIdx.x == 0){
        float ys = g_stat[b*8+0];
        s_c[0] = g_stat[b*8+1];
        s_c[1] = g_stat[b*8+2];
        s_c[2] = g_stat[b*8+4] / ys;
        s_c[3] = 2.f*(ys*g_stat[b*8+3] - g_stat[b*8+5]) / fmaxf(ys*ys, EPSV);
    }
    __syncthreads();
    float gi[3], gh[3];
    #pragma unroll
    for (int g = 0; g < 3; g++){
        int r = j + g*DMx;
        const float4 tl = *(const float4*)(Wih + (size_t)r * 516 + 512);
        gi[g] = g_gi[b*1536 + r]
              + tl.x*s_c[0] + tl.y*s_c[1] + tl.z*s_c[2] + tl.w*s_c[3];
        gh[g] = g_gh[b*1536 + r];
    }
    float rg = 1.f / (1.f + expf(-(gi[0] + gh[0])));
    float zg = 1.f / (1.f + expf(-(gi[1] + gh[1])));
    float ng = tanhf(gi[2] + rg * gh[2]);
    mem_out[b*DMx + j] = (1.f - zg) * ng + zg * mem_in[b*DMx + j];
}

// ---------------- launch ----------------
extern "C" void kernel_launch(void* const* d_in, const int* in_sizes, int n_in,
                              void* d_out, int out_size){
    const float* u    = (const float*)d_in[0];
    const float* sf   = (const float*)d_in[1];
    const float* sim  = (const float*)d_in[2];
    const float* mem0 = (const float*)d_in[3];
    const float* Wq   = (const float*)d_in[4];
    const float* Wk   = (const float*)d_in[5];
    const float* Wv   = (const float*)d_in[6];
    const float* sbw1 = (const float*)d_in[7];
    const float* sbb1 = (const float*)d_in[8];
    const float* sbw2 = (const float*)d_in[9];
    const float* sbb2 = (const float*)d_in[10];
    const float* lt   = (const float*)d_in[11];
    const float* Wih  = (const float*)d_in[12];
    const float* bih  = (const float*)d_in[13];
    const float* Whh  = (const float*)d_in[14];
    const float* bhh  = (const float*)d_in[15];
    float* out = (float*)d_out;

    static cudaStream_t s2 = nullptr, s3 = nullptr;
    static cudaEvent_t evR, evM, evC, evF[3], evJ[3], evY[4], evZ[4], evG[3], evGH[4], evGI[4];
    if (s2 == nullptr){
        cudaStreamCreateWithFlags(&s2, cudaStreamNonBlocking);
        cudaStreamCreateWithFlags(&s3, cudaStreamNonBlocking);
        cudaEventCreateWithFlags(&evR, cudaEventDisableTiming);
        cudaEventCreateWithFlags(&evM, cudaEventDisableTiming);
        cudaEventCreateWithFlags(&evC, cudaEventDisableTiming);
        for (int i = 0; i < 3; i++){
            cudaEventCreateWithFlags(&evF[i], cudaEventDisableTiming);
            cudaEventCreateWithFlags(&evJ[i], cudaEventDisableTiming);
            cudaEventCreateWithFlags(&evG[i], cudaEventDisableTiming);
        }
        for (int i = 0; i < 4; i++){
            cudaEventCreateWithFlags(&evY[i], cudaEventDisableTiming);
            cudaEventCreateWithFlags(&evZ[i], cudaEventDisableTiming);
            cudaEventCreateWithFlags(&evGH[i], cudaEventDisableTiming);
            cudaEventCreateWithFlags(&evGI[i], cudaEventDisableTiming);
        }
    }

    // prologue (3 streams): s2 = sim conversion; s3 = init+Mpre+gh0+Wcomb; main = pre+qk+scores
    cudaEventRecord(evR, 0);
    cudaStreamWaitEvent(s2, evR, 0);
    cudaStreamWaitEvent(s3, evR, 0);
    k_conv<<<8192, 256, 0, s2>>>(sim);
    cudaEventRecord(evC, s2);
    k_init<<<64, 256, 0, s3>>>(mem0);
    k_Mpre<<<256, 256, 0, s3>>>(Wk, Wq);
    cudaEventRecord(evM, s3);                          // M + memA + sp=0 ready
    k_gh<<<192, 256, 0, s3>>>(Whh, bhh, 0);            // gh for stage 0
    cudaEventRecord(evGH[0], s3);
    k_Wcomb<<<768, 256, 0, s3>>>(Wih, Wv);             // Wc ready before any gimain (s3 order)
    k_pre<<<BB*TT/16, 256>>>(u, sf, sbw1, sbb1, sbw2, sbb2);
    cudaStreamWaitEvent(0, evM, 0);
    k_qk<<<BB*16, 256>>>(0);
    k_scores<<<BB*TT/16, 256>>>();
    cudaStreamWaitEvent(0, evC, 0);                    // fp16 sim ready

    for (int s = 0; s < NSTAGE; s++){
        int inB = s & 1;
        int lastS = (s == NSTAGE - 1);
        if (s > 0){
            cudaStreamWaitEvent(0, evJ[s-1], 0);       // sp ready
            cudaStreamWaitEvent(0, evZ[s-1], 0);       // zx/gimain done before yu zeroed
        }
        k_simmv_ov<<<BB*TT/16, 256>>>(lt);             // softmax + fp16 overlap
        k_penalty<<<BB, 1024>>>(lt);
        if (!lastS){
            cudaEventRecord(evF[s], 0);
            cudaStreamWaitEvent(s2, evF[s], 0);
            k_simmv_sp<<<BB*TT/16, 256, 0, s2>>>();
            cudaEventRecord(evJ[s], s2);
        }
        k_yu<<<BB*64, 256>>>();
        cudaEventRecord(evY[s], 0);
        cudaStreamWaitEvent(s3, evY[s], 0);
        if (!lastS){
            k_gimain<<<192, 256, 0, s3>>>(bih);        // gi main matvec, parallel with dist
            cudaEventRecord(evGI[s], s3);
        }
        k_zx<<<BB*8, 256, 0, s3>>>(Wv, out, s);        // out only, off critical path
        cudaEventRecord(evZ[s], s3);
        if (!lastS){
            k_dist<<<BB*TT/16, 256>>>();               // spread + csq (2 rows/warp)
            cudaStreamWaitEvent(0, evGH[s], 0);
            cudaStreamWaitEvent(0, evGI[s], 0);
            k_grufin<<<BB, 512>>>(Wih, inB);           // tiny: tail + gates
            cudaEventRecord(evG[s], 0);
            cudaStreamWaitEvent(s3, evG[s], 0);
            k_gh<<<192, 256, 0, s3>>>(Whh, bhh, (s+1) & 1);
            cudaEventRecord(evGH[s+1], s3);
            k_qk<<<BB*16, 256>>>((s+1) & 1);
            k_scores<<<BB*TT/16, 256>>>();
        }
    }
    cudaStreamWaitEvent(0, evZ[NSTAGE-1], 0);          // join final s3 branch
}